// round 1
// baseline (speedup 1.0000x reference)
#include <cuda_runtime.h>
#include <math.h>

// ---------------- problem constants ----------------
#define BB     64
#define HH     56
#define WW_    56
#define CC     192
#define LL     (HH*WW_)            // 3136
#define MROWS  (BB*LL)             // 200704
#define NHEADS 6
#define HD     32
#define WS_    8
#define NT     64                  // tokens per window
#define NWIN   49                  // windows per image
#define BWIN   (BB*NWIN)           // 3136 total windows
#define HID    768
#define QKVN   576
#define SCALE_ 0.17677669529663687f  // 1/sqrt(32)

// ---------------- scratch (static device arrays; no allocation) ----------------
__device__ float g_xw  [(size_t)MROWS * CC];    // LN1 + shifted + windowed
__device__ float g_qkv [(size_t)MROWS * QKVN];  // qkv projection (windowed rows)
__device__ float g_attn[(size_t)MROWS * CC];    // attention output (windowed rows)
__device__ float g_xn2 [(size_t)MROWS * CC];    // LN2 output
__device__ float g_h1  [(size_t)MROWS * HID];   // MLP hidden

// map a windowed row index -> global token row index (handles shift +4 wrap,
// used both for gathering (partition) and scattering (reverse); the two
// mappings are identical because roll(-s) partition and reverse roll(+s)
// compose to the same permutation).
__device__ __forceinline__ int win_to_global(int wrow) {
    int b_  = wrow >> 6;        // / 64
    int n   = wrow & 63;
    int b   = b_ / NWIN;
    int wi  = b_ - b * NWIN;
    int hp  = (wi / 7) * 8 + (n >> 3);
    int wp  = (wi % 7) * 8 + (n & 7);
    int h = hp + 4; if (h >= HH)  h -= HH;
    int w = wp + 4; if (w >= WW_) w -= WW_;
    return b * LL + h * WW_ + w;
}

// ---------------- LayerNorm (192 threads = 1 row) ----------------
// MAP=true : output row `row` is LN of x[win_to_global(row)]  (LN1 + shift + partition)
// MAP=false: identity row mapping (LN2)
template<bool MAP>
__global__ void ln_kernel(const float* __restrict__ x,
                          const float* __restrict__ w,
                          const float* __restrict__ b,
                          float* __restrict__ out)
{
    int row = blockIdx.x;
    int tid = threadIdx.x;
    int g = MAP ? win_to_global(row) : row;
    float v = x[(size_t)g * CC + tid];

    __shared__ float sh[12];
    float s = v, s2 = v * v;
    #pragma unroll
    for (int o = 16; o; o >>= 1) {
        s  += __shfl_xor_sync(0xffffffffu, s,  o);
        s2 += __shfl_xor_sync(0xffffffffu, s2, o);
    }
    int wp = tid >> 5;
    if ((tid & 31) == 0) { sh[wp] = s; sh[6 + wp] = s2; }
    __syncthreads();
    float ts = 0.f, ts2 = 0.f;
    #pragma unroll
    for (int i = 0; i < 6; i++) { ts += sh[i]; ts2 += sh[6 + i]; }
    const float inv = 1.f / 192.f;
    float mu  = ts * inv;
    float var = ts2 * inv - mu * mu;
    float rs  = rsqrtf(var + 1e-5f);
    out[(size_t)row * CC + tid] = (v - mu) * rs * w[tid] + b[tid];
}

// ---------------- generic tiled fp32 GEMM ----------------
// C[M,N] = A[M,K] @ W[K,N] + bias, with epilogues:
//   EPI 0: plain store
//   EPI 1: exact GELU
//   EPI 2: window-reverse scatter + residual:  out[g] = res[g] + v   (g = win_to_global(m))
//   EPI 3: residual in place:                  out[m] = res[m] + v
// BM=128 BN=64 BK=16, 256 threads, 8x4 per-thread microtile.
template<int EPI>
__global__ void __launch_bounds__(256)
gemm_k(const float* __restrict__ A, const float* __restrict__ W,
       const float* __restrict__ bias, const float* __restrict__ res,
       float* __restrict__ Cout, int M, int N, int K)
{
    __shared__ float As[16][128];
    __shared__ float Ws[16][64];

    int tid = threadIdx.x;
    int bm = blockIdx.y * 128, bn = blockIdx.x * 64;
    int ty = tid >> 4, tx = tid & 15;
    int ar = tid >> 2, ac = (tid & 3) * 4;   // A loader: 2 rows x float4
    int wr = tid >> 4, wc = (tid & 15) * 4;  // W loader: 1 float4

    float acc[8][4];
    #pragma unroll
    for (int i = 0; i < 8; i++)
        #pragma unroll
        for (int j = 0; j < 4; j++) acc[i][j] = 0.f;

    const float* Ap0 = A + (size_t)(bm + ar)       * K + ac;
    const float* Ap1 = A + (size_t)(bm + ar + 64)  * K + ac;

    for (int k0 = 0; k0 < K; k0 += 16) {
        float4 a0 = *(const float4*)(Ap0 + k0);
        float4 a1 = *(const float4*)(Ap1 + k0);
        float4 w0 = *(const float4*)(W + (size_t)(k0 + wr) * N + bn + wc);

        As[ac + 0][ar] = a0.x; As[ac + 1][ar] = a0.y;
        As[ac + 2][ar] = a0.z; As[ac + 3][ar] = a0.w;
        As[ac + 0][ar + 64] = a1.x; As[ac + 1][ar + 64] = a1.y;
        As[ac + 2][ar + 64] = a1.z; As[ac + 3][ar + 64] = a1.w;
        *(float4*)&Ws[wr][wc] = w0;
        __syncthreads();

        #pragma unroll
        for (int kk = 0; kk < 16; kk++) {
            float4 ra0 = *(const float4*)&As[kk][ty * 8];
            float4 ra1 = *(const float4*)&As[kk][ty * 8 + 4];
            float4 rb  = *(const float4*)&Ws[kk][tx * 4];
            float a[8] = {ra0.x, ra0.y, ra0.z, ra0.w, ra1.x, ra1.y, ra1.z, ra1.w};
            float bv[4] = {rb.x, rb.y, rb.z, rb.w};
            #pragma unroll
            for (int i = 0; i < 8; i++)
                #pragma unroll
                for (int j = 0; j < 4; j++)
                    acc[i][j] = fmaf(a[i], bv[j], acc[i][j]);
        }
        __syncthreads();
    }

    #pragma unroll
    for (int i = 0; i < 8; i++) {
        int m = bm + ty * 8 + i;
        int gm = (EPI == 2) ? win_to_global(m) : m;
        #pragma unroll
        for (int j = 0; j < 4; j++) {
            int n = bn + tx * 4 + j;
            float v = acc[i][j] + bias[n];
            if (EPI == 1) v = 0.5f * v * (1.f + erff(v * 0.70710678118654752f));
            if (EPI == 2) v += res[(size_t)gm * N + n];
            if (EPI == 3) v += res[(size_t)m  * N + n];
            Cout[(size_t)gm * N + n] = v;
        }
    }
}

// ---------------- windowed attention ----------------
// grid = (BWIN, NHEADS), 64 threads (one per query token).
// qkv rows are in windowed order. Bias + shift-mask computed in-kernel.
__global__ void __launch_bounds__(64)
attn_kernel(const float* __restrict__ qkv, const float* __restrict__ rpb,
            float* __restrict__ out)
{
    int b_ = blockIdx.x;
    int h  = blockIdx.y;
    int tid = threadIdx.x;

    __shared__ float ks[NT][HD];
    __shared__ float vs[NT][HD];
    __shared__ float bias_s[225];
    __shared__ int   reg_s[NT];

    const float* base = qkv + (size_t)b_ * NT * QKVN;

    // cooperative K/V load
    for (int idx = tid; idx < NT * HD; idx += 64) {
        int r = idx >> 5, d = idx & 31;
        ks[r][d] = base[r * QKVN + 192 + h * HD + d];
        vs[r][d] = base[r * QKVN + 384 + h * HD + d];
    }
    // relative position bias for this head
    for (int i = tid; i < 225; i += 64) bias_s[i] = rpb[i * NHEADS + h];

    // shift-mask region id per token (unshifted-grid regions, as in reference)
    {
        int wi = b_ % NWIN;
        int r = tid >> 3, c = tid & 7;
        int gh = (wi / 7) * 8 + r;
        int gw = (wi % 7) * 8 + c;
        int rh = (gh < 48) ? 0 : (gh < 52 ? 1 : 2);
        int rw = (gw < 48) ? 0 : (gw < 52 ? 1 : 2);
        reg_s[tid] = rh * 3 + rw;
    }
    __syncthreads();

    // my query row
    float q[HD];
    #pragma unroll
    for (int d = 0; d < HD; d++) q[d] = base[tid * QKVN + h * HD + d] * SCALE_;

    int r1 = tid >> 3, c1 = tid & 7;
    int myreg = reg_s[tid];

    float s[NT];
    float mx = -1e30f;
    #pragma unroll 4
    for (int m = 0; m < NT; m++) {
        float dot = 0.f;
        #pragma unroll
        for (int d = 0; d < HD; d += 4) {
            float4 kv = *(const float4*)&ks[m][d];
            dot = fmaf(q[d + 0], kv.x, dot);
            dot = fmaf(q[d + 1], kv.y, dot);
            dot = fmaf(q[d + 2], kv.z, dot);
            dot = fmaf(q[d + 3], kv.w, dot);
        }
        int r2 = m >> 3, c2 = m & 7;
        dot += bias_s[(r1 - r2 + 7) * 15 + (c1 - c2 + 7)];
        if (reg_s[m] != myreg) dot -= 100.f;
        s[m] = dot;
        mx = fmaxf(mx, dot);
    }

    float sum = 0.f;
    #pragma unroll
    for (int m = 0; m < NT; m++) { s[m] = __expf(s[m] - mx); sum += s[m]; }
    float rinv = 1.f / sum;

    float acc[HD];
    #pragma unroll
    for (int d = 0; d < HD; d++) acc[d] = 0.f;
    #pragma unroll 4
    for (int m = 0; m < NT; m++) {
        float p = s[m] * rinv;
        #pragma unroll
        for (int d = 0; d < HD; d += 4) {
            float4 vv = *(const float4*)&vs[m][d];
            acc[d + 0] = fmaf(p, vv.x, acc[d + 0]);
            acc[d + 1] = fmaf(p, vv.y, acc[d + 1]);
            acc[d + 2] = fmaf(p, vv.z, acc[d + 2]);
            acc[d + 3] = fmaf(p, vv.w, acc[d + 3]);
        }
    }

    float* orow = out + (size_t)(b_ * NT + tid) * CC + h * HD;
    #pragma unroll
    for (int d = 0; d < HD; d += 4)
        *(float4*)&orow[d] = make_float4(acc[d], acc[d + 1], acc[d + 2], acc[d + 3]);
}

// ---------------- launch ----------------
extern "C" void kernel_launch(void* const* d_in, const int* in_sizes, int n_in,
                              void* d_out, int out_size)
{
    const float* x      = (const float*)d_in[0];
    const float* ln1_w  = (const float*)d_in[1];
    const float* ln1_b  = (const float*)d_in[2];
    const float* qkv_w  = (const float*)d_in[3];
    const float* qkv_b  = (const float*)d_in[4];
    const float* proj_w = (const float*)d_in[5];
    const float* proj_b = (const float*)d_in[6];
    const float* rpb    = (const float*)d_in[7];
    const float* ln2_w  = (const float*)d_in[8];
    const float* ln2_b  = (const float*)d_in[9];
    const float* fc1_w  = (const float*)d_in[10];
    const float* fc1_b  = (const float*)d_in[11];
    const float* fc2_w  = (const float*)d_in[12];
    const float* fc2_b  = (const float*)d_in[13];
    float* out = (float*)d_out;

    float *xw, *qkv, *attn, *xn2, *h1;
    cudaGetSymbolAddress((void**)&xw,   g_xw);
    cudaGetSymbolAddress((void**)&qkv,  g_qkv);
    cudaGetSymbolAddress((void**)&attn, g_attn);
    cudaGetSymbolAddress((void**)&xn2,  g_xn2);
    cudaGetSymbolAddress((void**)&h1,   g_h1);

    // 1. LN1 + shift + window partition
    ln_kernel<true><<<MROWS, CC>>>(x, ln1_w, ln1_b, xw);
    // 2. qkv = xw @ qkv_w + b            [200704,192] x [192,576]
    gemm_k<0><<<dim3(QKVN / 64, MROWS / 128), 256>>>(xw, qkv_w, qkv_b, nullptr, qkv,
                                                     MROWS, QKVN, CC);
    // 3. windowed attention
    attn_kernel<<<dim3(BWIN, NHEADS), 64>>>(qkv, rpb, attn);
    // 4. proj + window-reverse + unshift + residual -> y (in d_out)
    gemm_k<2><<<dim3(CC / 64, MROWS / 128), 256>>>(attn, proj_w, proj_b, x, out,
                                                   MROWS, CC, CC);
    // 5. LN2
    ln_kernel<false><<<MROWS, CC>>>(out, ln2_w, ln2_b, xn2);
    // 6. fc1 + GELU
    gemm_k<1><<<dim3(HID / 64, MROWS / 128), 256>>>(xn2, fc1_w, fc1_b, nullptr, h1,
                                                    MROWS, HID, CC);
    // 7. fc2 + residual (in-place on d_out)
    gemm_k<3><<<dim3(CC / 64, MROWS / 128), 256>>>(h1, fc2_w, fc2_b, out, out,
                                                   MROWS, CC, HID);
}

// round 2
// speedup vs baseline: 2.1870x; 2.1870x over previous
#include <cuda_runtime.h>
#include <math.h>
#include <stdint.h>

// ---------------- problem constants ----------------
#define BB     64
#define HH     56
#define WW_    56
#define CC     192
#define LL     (HH*WW_)            // 3136
#define MROWS  (BB*LL)             // 200704
#define NHEADS 6
#define HD     32
#define NT     64                  // tokens per window
#define NWIN   49                  // windows per image
#define BWIN   (BB*NWIN)           // 3136 total windows
#define HID    768
#define QKVN   576
#define SCALE_ 0.17677669529663687f  // 1/sqrt(32)

// GEMM tiling
#define BM 256
#define BN 64
#define BK 32
#define LDA 36   // As row stride (floats): (4m+k) mod 32 distinct -> conflict-free frags
#define LDB 72   // Bs row stride (floats): (8k+n) mod 32 distinct -> conflict-free frags
#define SMEM_BYTES ((2*BM*LDA + 2*BK*LDB) * 4)   // 92160

// ---------------- scratch (static device arrays; no allocation) ----------------
__device__ float g_xw  [(size_t)MROWS * CC];    // LN1 + shifted + windowed (tf32-rounded)
__device__ float g_qkv [(size_t)MROWS * QKVN];  // qkv projection
__device__ float g_attn[(size_t)MROWS * CC];    // attention output (tf32-rounded)
__device__ float g_xn2 [(size_t)MROWS * CC];    // LN2 output (tf32-rounded)
__device__ float g_h1  [(size_t)MROWS * HID];   // MLP hidden (tf32-rounded)
__device__ float g_wr  [110592 + 36864 + 147456 + 147456]; // tf32-rounded weights

#define WOFF_QKV  0
#define WOFF_PROJ 110592
#define WOFF_FC1  147456
#define WOFF_FC2  294912

// round fp32 -> nearest tf32 (keeps fp32 container, low 13 bits zero)
__device__ __forceinline__ float rtf32(float x) {
    uint32_t u;
    asm("cvt.rna.tf32.f32 %0, %1;" : "=r"(u) : "f"(x));
    return __uint_as_float(u);
}

__device__ __forceinline__ uint32_t smem_u32(const void* p) {
    uint32_t a;
    asm("{.reg .u64 t; cvta.to.shared.u64 t, %1; cvt.u32.u64 %0, t;}" : "=r"(a) : "l"(p));
    return a;
}
__device__ __forceinline__ void cp_async16(uint32_t dst, const void* src) {
    asm volatile("cp.async.cg.shared.global [%0], [%1], 16;\n" :: "r"(dst), "l"(src));
}

// map windowed row index -> global token row index (shift +4 wrap)
__device__ __forceinline__ int win_to_global(int wrow) {
    int b_  = wrow >> 6;
    int n   = wrow & 63;
    int b   = b_ / NWIN;
    int wi  = b_ - b * NWIN;
    int hp  = (wi / 7) * 8 + (n >> 3);
    int wp  = (wi % 7) * 8 + (n & 7);
    int h = hp + 4; if (h >= HH)  h -= HH;
    int w = wp + 4; if (w >= WW_) w -= WW_;
    return b * LL + h * WW_ + w;
}

// ---------------- weight pre-rounding ----------------
__global__ void prep_w_kernel(const float* __restrict__ qkv_w,
                              const float* __restrict__ proj_w,
                              const float* __restrict__ fc1_w,
                              const float* __restrict__ fc2_w)
{
    int i = blockIdx.x * 256 + threadIdx.x;
    if (i < 110592) g_wr[WOFF_QKV  + i] = rtf32(qkv_w[i]);
    if (i < 36864)  g_wr[WOFF_PROJ + i] = rtf32(proj_w[i]);
    if (i < 147456) {
        g_wr[WOFF_FC1 + i] = rtf32(fc1_w[i]);
        g_wr[WOFF_FC2 + i] = rtf32(fc2_w[i]);
    }
}

// ---------------- LayerNorm (192 threads = 1 row); stores tf32-rounded ----------------
template<bool MAP>
__global__ void ln_kernel(const float* __restrict__ x,
                          const float* __restrict__ w,
                          const float* __restrict__ b,
                          float* __restrict__ out)
{
    int row = blockIdx.x;
    int tid = threadIdx.x;
    int g = MAP ? win_to_global(row) : row;
    float v = x[(size_t)g * CC + tid];

    __shared__ float sh[12];
    float s = v, s2 = v * v;
    #pragma unroll
    for (int o = 16; o; o >>= 1) {
        s  += __shfl_xor_sync(0xffffffffu, s,  o);
        s2 += __shfl_xor_sync(0xffffffffu, s2, o);
    }
    int wp = tid >> 5;
    if ((tid & 31) == 0) { sh[wp] = s; sh[6 + wp] = s2; }
    __syncthreads();
    float ts = 0.f, ts2 = 0.f;
    #pragma unroll
    for (int i = 0; i < 6; i++) { ts += sh[i]; ts2 += sh[6 + i]; }
    const float inv = 1.f / 192.f;
    float mu  = ts * inv;
    float var = ts2 * inv - mu * mu;
    float rs  = rsqrtf(var + 1e-5f);
    out[(size_t)row * CC + tid] = rtf32((v - mu) * rs * w[tid] + b[tid]);
}

// ---------------- tf32 tensor-core GEMM ----------------
// C[M,N] = A[M,K] @ W[K,N] + bias, epilogues:
//   EPI 0: plain store
//   EPI 1: exact GELU, tf32-rounded (feeds fc2)
//   EPI 2: window-reverse scatter + residual:  out[g] = res[g] + v
//   EPI 3: residual in place:                  out[m] = res[m] + v
// BM=256 BN=64 BK=32, 256 thr = 8 warps (4x2), warp tile 64x32, mma.m16n8k8.tf32,
// cp.async double-buffered smem.
template<int EPI>
__global__ void __launch_bounds__(256)
gemm_tc(const float* __restrict__ A, const float* __restrict__ W,
        const float* __restrict__ bias, const float* __restrict__ res,
        float* __restrict__ Cout, int M, int N, int K)
{
    extern __shared__ float smem[];
    float* As = smem;                    // [2][BM][LDA]
    float* Bs = smem + 2 * BM * LDA;     // [2][BK][LDB]

    const int tid  = threadIdx.x;
    const int wid  = tid >> 5, lane = tid & 31;
    const int bm   = blockIdx.y * BM, bn = blockIdx.x * BN;
    const int warp_m = (wid >> 1) * 64;  // 0,64,128,192
    const int warp_n = (wid & 1) * 32;   // 0,32

    float acc[4][4][4];
    #pragma unroll
    for (int f = 0; f < 4; f++)
        #pragma unroll
        for (int g = 0; g < 4; g++)
            #pragma unroll
            for (int r = 0; r < 4; r++) acc[f][g][r] = 0.f;

    // tile loader: A 256x32 (2048 float4, 8/thread), B 32x64 (512 float4, 2/thread)
    auto load_tiles = [&](int k0, int stage) {
        float* as = As + stage * (BM * LDA);
        float* bs = Bs + stage * (BK * LDB);
        #pragma unroll
        for (int i = 0; i < 8; i++) {
            int idx = tid + i * 256;
            int r = idx >> 3, c4 = (idx & 7) << 2;
            cp_async16(smem_u32(&as[r * LDA + c4]),
                       A + (size_t)(bm + r) * K + k0 + c4);
        }
        #pragma unroll
        for (int i = 0; i < 2; i++) {
            int idx = tid + i * 256;
            int r = idx >> 4, c4 = (idx & 15) << 2;
            cp_async16(smem_u32(&bs[r * LDB + c4]),
                       W + (size_t)(k0 + r) * N + bn + c4);
        }
        asm volatile("cp.async.commit_group;\n");
    };

    load_tiles(0, 0);
    asm volatile("cp.async.wait_group 0;\n");
    __syncthreads();

    const int KT = K >> 5;
    for (int kt = 0; kt < KT; kt++) {
        int stage = kt & 1;
        if (kt + 1 < KT) load_tiles((kt + 1) << 5, stage ^ 1);

        const float* as = As + stage * (BM * LDA) + warp_m * LDA;
        const float* bs = Bs + stage * (BK * LDB) + warp_n;

        #pragma unroll
        for (int ks = 0; ks < 4; ks++) {
            int k = ks * 8;
            uint32_t a[4][4];
            #pragma unroll
            for (int f = 0; f < 4; f++) {
                const float* ap = as + (f * 16 + (lane >> 2)) * LDA + k + (lane & 3);
                a[f][0] = __float_as_uint(ap[0]);
                a[f][1] = __float_as_uint(ap[8 * LDA]);
                a[f][2] = __float_as_uint(ap[4]);
                a[f][3] = __float_as_uint(ap[8 * LDA + 4]);
            }
            uint32_t b[4][2];
            #pragma unroll
            for (int g = 0; g < 4; g++) {
                const float* bp = bs + (k + (lane & 3)) * LDB + g * 8 + (lane >> 2);
                b[g][0] = __float_as_uint(bp[0]);
                b[g][1] = __float_as_uint(bp[4 * LDB]);
            }
            #pragma unroll
            for (int f = 0; f < 4; f++)
                #pragma unroll
                for (int g = 0; g < 4; g++) {
                    float* c = acc[f][g];
                    asm volatile(
                        "mma.sync.aligned.m16n8k8.row.col.f32.tf32.tf32.f32 "
                        "{%0,%1,%2,%3}, {%4,%5,%6,%7}, {%8,%9}, {%0,%1,%2,%3};\n"
                        : "+f"(c[0]), "+f"(c[1]), "+f"(c[2]), "+f"(c[3])
                        : "r"(a[f][0]), "r"(a[f][1]), "r"(a[f][2]), "r"(a[f][3]),
                          "r"(b[g][0]), "r"(b[g][1]));
                }
        }
        asm volatile("cp.async.wait_group 0;\n");
        __syncthreads();
    }

    // epilogue
    #pragma unroll
    for (int f = 0; f < 4; f++) {
        #pragma unroll
        for (int i = 0; i < 2; i++) {
            int m  = bm + warp_m + f * 16 + (lane >> 2) + i * 8;
            int gm = (EPI == 2) ? win_to_global(m) : m;
            #pragma unroll
            for (int g = 0; g < 4; g++) {
                int n = bn + warp_n + g * 8 + ((lane & 3) << 1);
                float v0 = acc[f][g][i * 2 + 0] + bias[n];
                float v1 = acc[f][g][i * 2 + 1] + bias[n + 1];
                if (EPI == 1) {
                    v0 = rtf32(0.5f * v0 * (1.f + erff(v0 * 0.70710678118654752f)));
                    v1 = rtf32(0.5f * v1 * (1.f + erff(v1 * 0.70710678118654752f)));
                }
                if (EPI == 2) {
                    const float2 r2 = *(const float2*)&res[(size_t)gm * N + n];
                    v0 += r2.x; v1 += r2.y;
                }
                if (EPI == 3) {
                    const float2 r2 = *(const float2*)&res[(size_t)m * N + n];
                    v0 += r2.x; v1 += r2.y;
                }
                *(float2*)&Cout[(size_t)gm * N + n] = make_float2(v0, v1);
            }
        }
    }
}

// ---------------- windowed attention ----------------
__global__ void __launch_bounds__(64)
attn_kernel(const float* __restrict__ qkv, const float* __restrict__ rpb,
            float* __restrict__ out)
{
    int b_ = blockIdx.x;
    int h  = blockIdx.y;
    int tid = threadIdx.x;

    __shared__ float ks[NT][HD];
    __shared__ float vs[NT][HD];
    __shared__ float bias_s[225];
    __shared__ int   reg_s[NT];

    const float* base = qkv + (size_t)b_ * NT * QKVN;

    for (int idx = tid; idx < NT * HD; idx += 64) {
        int r = idx >> 5, d = idx & 31;
        ks[r][d] = base[r * QKVN + 192 + h * HD + d];
        vs[r][d] = base[r * QKVN + 384 + h * HD + d];
    }
    for (int i = tid; i < 225; i += 64) bias_s[i] = rpb[i * NHEADS + h];
    {
        int wi = b_ % NWIN;
        int r = tid >> 3, c = tid & 7;
        int gh = (wi / 7) * 8 + r;
        int gw = (wi % 7) * 8 + c;
        int rh = (gh < 48) ? 0 : (gh < 52 ? 1 : 2);
        int rw = (gw < 48) ? 0 : (gw < 52 ? 1 : 2);
        reg_s[tid] = rh * 3 + rw;
    }
    __syncthreads();

    float q[HD];
    #pragma unroll
    for (int d = 0; d < HD; d++) q[d] = base[tid * QKVN + h * HD + d] * SCALE_;

    int r1 = tid >> 3, c1 = tid & 7;
    int myreg = reg_s[tid];

    float s[NT];
    float mx = -1e30f;
    #pragma unroll 4
    for (int m = 0; m < NT; m++) {
        float dot = 0.f;
        #pragma unroll
        for (int d = 0; d < HD; d += 4) {
            float4 kv = *(const float4*)&ks[m][d];
            dot = fmaf(q[d + 0], kv.x, dot);
            dot = fmaf(q[d + 1], kv.y, dot);
            dot = fmaf(q[d + 2], kv.z, dot);
            dot = fmaf(q[d + 3], kv.w, dot);
        }
        int r2 = m >> 3, c2 = m & 7;
        dot += bias_s[(r1 - r2 + 7) * 15 + (c1 - c2 + 7)];
        if (reg_s[m] != myreg) dot -= 100.f;
        s[m] = dot;
        mx = fmaxf(mx, dot);
    }

    float sum = 0.f;
    #pragma unroll
    for (int m = 0; m < NT; m++) { s[m] = __expf(s[m] - mx); sum += s[m]; }
    float rinv = 1.f / sum;

    float acc[HD];
    #pragma unroll
    for (int d = 0; d < HD; d++) acc[d] = 0.f;
    #pragma unroll 4
    for (int m = 0; m < NT; m++) {
        float p = s[m] * rinv;
        #pragma unroll
        for (int d = 0; d < HD; d += 4) {
            float4 vv = *(const float4*)&vs[m][d];
            acc[d + 0] = fmaf(p, vv.x, acc[d + 0]);
            acc[d + 1] = fmaf(p, vv.y, acc[d + 1]);
            acc[d + 2] = fmaf(p, vv.z, acc[d + 2]);
            acc[d + 3] = fmaf(p, vv.w, acc[d + 3]);
        }
    }

    float* orow = out + (size_t)(b_ * NT + tid) * CC + h * HD;
    #pragma unroll
    for (int d = 0; d < HD; d += 4)
        *(float4*)&orow[d] = make_float4(rtf32(acc[d]),     rtf32(acc[d + 1]),
                                         rtf32(acc[d + 2]), rtf32(acc[d + 3]));
}

// ---------------- launch ----------------
extern "C" void kernel_launch(void* const* d_in, const int* in_sizes, int n_in,
                              void* d_out, int out_size)
{
    const float* x      = (const float*)d_in[0];
    const float* ln1_w  = (const float*)d_in[1];
    const float* ln1_b  = (const float*)d_in[2];
    const float* qkv_w  = (const float*)d_in[3];
    const float* qkv_b  = (const float*)d_in[4];
    const float* proj_w = (const float*)d_in[5];
    const float* proj_b = (const float*)d_in[6];
    const float* rpb    = (const float*)d_in[7];
    const float* ln2_w  = (const float*)d_in[8];
    const float* ln2_b  = (const float*)d_in[9];
    const float* fc1_w  = (const float*)d_in[10];
    const float* fc1_b  = (const float*)d_in[11];
    const float* fc2_w  = (const float*)d_in[12];
    const float* fc2_b  = (const float*)d_in[13];
    float* out = (float*)d_out;

    float *xw, *qkv, *attn, *xn2, *h1, *wr;
    cudaGetSymbolAddress((void**)&xw,   g_xw);
    cudaGetSymbolAddress((void**)&qkv,  g_qkv);
    cudaGetSymbolAddress((void**)&attn, g_attn);
    cudaGetSymbolAddress((void**)&xn2,  g_xn2);
    cudaGetSymbolAddress((void**)&h1,   g_h1);
    cudaGetSymbolAddress((void**)&wr,   g_wr);

    cudaFuncSetAttribute(gemm_tc<0>, cudaFuncAttributeMaxDynamicSharedMemorySize, SMEM_BYTES);
    cudaFuncSetAttribute(gemm_tc<1>, cudaFuncAttributeMaxDynamicSharedMemorySize, SMEM_BYTES);
    cudaFuncSetAttribute(gemm_tc<2>, cudaFuncAttributeMaxDynamicSharedMemorySize, SMEM_BYTES);
    cudaFuncSetAttribute(gemm_tc<3>, cudaFuncAttributeMaxDynamicSharedMemorySize, SMEM_BYTES);

    // 0. round weights to tf32
    prep_w_kernel<<<(147456 + 255) / 256, 256>>>(qkv_w, proj_w, fc1_w, fc2_w);
    // 1. LN1 + shift + window partition
    ln_kernel<true><<<MROWS, CC>>>(x, ln1_w, ln1_b, xw);
    // 2. qkv = xw @ qkv_w + b
    gemm_tc<0><<<dim3(QKVN / BN, MROWS / BM), 256, SMEM_BYTES>>>(
        xw, wr + WOFF_QKV, qkv_b, nullptr, qkv, MROWS, QKVN, CC);
    // 3. windowed attention
    attn_kernel<<<dim3(BWIN, NHEADS), 64>>>(qkv, rpb, attn);
    // 4. proj + window-reverse + unshift + residual -> y (d_out)
    gemm_tc<2><<<dim3(CC / BN, MROWS / BM), 256, SMEM_BYTES>>>(
        attn, wr + WOFF_PROJ, proj_b, x, out, MROWS, CC, CC);
    // 5. LN2
    ln_kernel<false><<<MROWS, CC>>>(out, ln2_w, ln2_b, xn2);
    // 6. fc1 + GELU
    gemm_tc<1><<<dim3(HID / BN, MROWS / BM), 256, SMEM_BYTES>>>(
        xn2, wr + WOFF_FC1, fc1_b, nullptr, h1, MROWS, HID, CC);
    // 7. fc2 + residual (in-place on d_out)
    gemm_tc<3><<<dim3(CC / BN, MROWS / BM), 256, SMEM_BYTES>>>(
        h1, wr + WOFF_FC2, fc2_b, out, out, MROWS, CC, HID);
}

// round 5
// speedup vs baseline: 2.5629x; 1.1719x over previous
#include <cuda_runtime.h>
#include <math.h>
#include <stdint.h>

// ---------------- problem constants ----------------
#define BB     64
#define HH     56
#define WW_    56
#define CC     192
#define LL     (HH*WW_)            // 3136
#define MROWS  (BB*LL)             // 200704
#define NHEADS 6
#define HD     32
#define NT     64                  // tokens per window
#define NWIN   49                  // windows per image
#define BWIN   (BB*NWIN)           // 3136 total windows
#define HID    768
#define QKVN   576
#define SCALE_ 0.17677669529663687f  // 1/sqrt(32)

// GEMM tiling
#define BM 256
#define BN 64
#define BK 32
#define LDA 36
#define LDB 72
#define SMEM_BYTES ((2*BM*LDA + 2*BK*LDB) * 4)   // 92160

// ---------------- scratch ----------------
__device__ float g_xw  [(size_t)MROWS * CC];
__device__ float g_qkv [(size_t)MROWS * QKVN];
__device__ float g_attn[(size_t)MROWS * CC];
__device__ float g_xn2 [(size_t)MROWS * CC];
__device__ float g_h1  [(size_t)MROWS * HID];
__device__ float g_wr  [110592 + 36864 + 147456 + 147456];

#define WOFF_QKV  0
#define WOFF_PROJ 110592
#define WOFF_FC1  147456
#define WOFF_FC2  294912

__device__ __forceinline__ float rtf32(float x) {
    uint32_t u;
    asm("cvt.rna.tf32.f32 %0, %1;" : "=r"(u) : "f"(x));
    return __uint_as_float(u);
}
__device__ __forceinline__ uint32_t smem_u32(const void* p) {
    uint32_t a;
    asm("{.reg .u64 t; cvta.to.shared.u64 t, %1; cvt.u32.u64 %0, t;}" : "=r"(a) : "l"(p));
    return a;
}
__device__ __forceinline__ void cp_async16(uint32_t dst, const void* src) {
    asm volatile("cp.async.cg.shared.global [%0], [%1], 16;\n" :: "r"(dst), "l"(src));
}
__device__ __forceinline__ void mma_tf32(float* c, const uint32_t* a, const uint32_t* b) {
    asm volatile(
        "mma.sync.aligned.m16n8k8.row.col.f32.tf32.tf32.f32 "
        "{%0,%1,%2,%3}, {%4,%5,%6,%7}, {%8,%9}, {%0,%1,%2,%3};\n"
        : "+f"(c[0]), "+f"(c[1]), "+f"(c[2]), "+f"(c[3])
        : "r"(a[0]), "r"(a[1]), "r"(a[2]), "r"(a[3]), "r"(b[0]), "r"(b[1]));
}

__device__ __forceinline__ int win_to_global(int wrow) {
    int b_  = wrow >> 6;
    int n   = wrow & 63;
    int b   = b_ / NWIN;
    int wi  = b_ - b * NWIN;
    int hp  = (wi / 7) * 8 + (n >> 3);
    int wp  = (wi % 7) * 8 + (n & 7);
    int h = hp + 4; if (h >= HH)  h -= HH;
    int w = wp + 4; if (w >= WW_) w -= WW_;
    return b * LL + h * WW_ + w;
}

// ---------------- weight pre-rounding ----------------
__global__ void prep_w_kernel(const float* __restrict__ qkv_w,
                              const float* __restrict__ proj_w,
                              const float* __restrict__ fc1_w,
                              const float* __restrict__ fc2_w)
{
    int i = blockIdx.x * 256 + threadIdx.x;
    if (i < 110592) g_wr[WOFF_QKV  + i] = rtf32(qkv_w[i]);
    if (i < 36864)  g_wr[WOFF_PROJ + i] = rtf32(proj_w[i]);
    if (i < 147456) {
        g_wr[WOFF_FC1 + i] = rtf32(fc1_w[i]);
        g_wr[WOFF_FC2 + i] = rtf32(fc2_w[i]);
    }
}

// ---------------- LayerNorm ----------------
template<bool MAP>
__global__ void ln_kernel(const float* __restrict__ x,
                          const float* __restrict__ w,
                          const float* __restrict__ b,
                          float* __restrict__ out)
{
    int row = blockIdx.x;
    int tid = threadIdx.x;
    int g = MAP ? win_to_global(row) : row;
    float v = x[(size_t)g * CC + tid];

    __shared__ float sh[12];
    float s = v, s2 = v * v;
    #pragma unroll
    for (int o = 16; o; o >>= 1) {
        s  += __shfl_xor_sync(0xffffffffu, s,  o);
        s2 += __shfl_xor_sync(0xffffffffu, s2, o);
    }
    int wp = tid >> 5;
    if ((tid & 31) == 0) { sh[wp] = s; sh[6 + wp] = s2; }
    __syncthreads();
    float ts = 0.f, ts2 = 0.f;
    #pragma unroll
    for (int i = 0; i < 6; i++) { ts += sh[i]; ts2 += sh[6 + i]; }
    const float inv = 1.f / 192.f;
    float mu  = ts * inv;
    float var = ts2 * inv - mu * mu;
    float rs  = rsqrtf(var + 1e-5f);
    out[(size_t)row * CC + tid] = rtf32((v - mu) * rs * w[tid] + b[tid]);
}

// ---------------- tf32 tensor-core GEMM (unchanged from R2) ----------------
template<int EPI>
__global__ void __launch_bounds__(256)
gemm_tc(const float* __restrict__ A, const float* __restrict__ W,
        const float* __restrict__ bias, const float* __restrict__ res,
        float* __restrict__ Cout, int M, int N, int K)
{
    extern __shared__ float smem[];
    float* As = smem;
    float* Bs = smem + 2 * BM * LDA;

    const int tid  = threadIdx.x;
    const int wid  = tid >> 5, lane = tid & 31;
    const int bm   = blockIdx.y * BM, bn = blockIdx.x * BN;
    const int warp_m = (wid >> 1) * 64;
    const int warp_n = (wid & 1) * 32;

    float acc[4][4][4];
    #pragma unroll
    for (int f = 0; f < 4; f++)
        #pragma unroll
        for (int g = 0; g < 4; g++)
            #pragma unroll
            for (int r = 0; r < 4; r++) acc[f][g][r] = 0.f;

    auto load_tiles = [&](int k0, int stage) {
        float* as = As + stage * (BM * LDA);
        float* bs = Bs + stage * (BK * LDB);
        #pragma unroll
        for (int i = 0; i < 8; i++) {
            int idx = tid + i * 256;
            int r = idx >> 3, c4 = (idx & 7) << 2;
            cp_async16(smem_u32(&as[r * LDA + c4]),
                       A + (size_t)(bm + r) * K + k0 + c4);
        }
        #pragma unroll
        for (int i = 0; i < 2; i++) {
            int idx = tid + i * 256;
            int r = idx >> 4, c4 = (idx & 15) << 2;
            cp_async16(smem_u32(&bs[r * LDB + c4]),
                       W + (size_t)(k0 + r) * N + bn + c4);
        }
        asm volatile("cp.async.commit_group;\n");
    };

    load_tiles(0, 0);
    asm volatile("cp.async.wait_group 0;\n");
    __syncthreads();

    const int KT = K >> 5;
    for (int kt = 0; kt < KT; kt++) {
        int stage = kt & 1;
        if (kt + 1 < KT) load_tiles((kt + 1) << 5, stage ^ 1);

        const float* as = As + stage * (BM * LDA) + warp_m * LDA;
        const float* bs = Bs + stage * (BK * LDB) + warp_n;

        #pragma unroll
        for (int ks = 0; ks < 4; ks++) {
            int k = ks * 8;
            uint32_t a[4][4];
            #pragma unroll
            for (int f = 0; f < 4; f++) {
                const float* ap = as + (f * 16 + (lane >> 2)) * LDA + k + (lane & 3);
                a[f][0] = __float_as_uint(ap[0]);
                a[f][1] = __float_as_uint(ap[8 * LDA]);
                a[f][2] = __float_as_uint(ap[4]);
                a[f][3] = __float_as_uint(ap[8 * LDA + 4]);
            }
            uint32_t b[4][2];
            #pragma unroll
            for (int g = 0; g < 4; g++) {
                const float* bp = bs + (k + (lane & 3)) * LDB + g * 8 + (lane >> 2);
                b[g][0] = __float_as_uint(bp[0]);
                b[g][1] = __float_as_uint(bp[4 * LDB]);
            }
            #pragma unroll
            for (int f = 0; f < 4; f++)
                #pragma unroll
                for (int g = 0; g < 4; g++)
                    mma_tf32(acc[f][g], a[f], b[g]);
        }
        asm volatile("cp.async.wait_group 0;\n");
        __syncthreads();
    }

    #pragma unroll
    for (int f = 0; f < 4; f++) {
        #pragma unroll
        for (int i = 0; i < 2; i++) {
            int m  = bm + warp_m + f * 16 + (lane >> 2) + i * 8;
            int gm = (EPI == 2) ? win_to_global(m) : m;
            #pragma unroll
            for (int g = 0; g < 4; g++) {
                int n = bn + warp_n + g * 8 + ((lane & 3) << 1);
                float v0 = acc[f][g][i * 2 + 0] + bias[n];
                float v1 = acc[f][g][i * 2 + 1] + bias[n + 1];
                if (EPI == 1) {
                    v0 = rtf32(0.5f * v0 * (1.f + erff(v0 * 0.70710678118654752f)));
                    v1 = rtf32(0.5f * v1 * (1.f + erff(v1 * 0.70710678118654752f)));
                }
                if (EPI == 2) {
                    const float2 r2 = *(const float2*)&res[(size_t)gm * N + n];
                    v0 += r2.x; v1 += r2.y;
                }
                if (EPI == 3) {
                    const float2 r2 = *(const float2*)&res[(size_t)m * N + n];
                    v0 += r2.x; v1 += r2.y;
                }
                *(float2*)&Cout[(size_t)gm * N + n] = make_float2(v0, v1);
            }
        }
    }
}

// ---------------- tensor-core windowed attention ----------------
__global__ void __launch_bounds__(64)
attn_mma_kernel(const float* __restrict__ qkv, const float* __restrict__ rpb,
                float* __restrict__ out)
{
    const int b_   = blockIdx.x;
    const int h    = blockIdx.y;
    const int tid  = threadIdx.x;
    const int warp = tid >> 5, lane = tid & 31;

    __shared__ float Ks[NT][36];
    __shared__ float Vs[NT][40];
    __shared__ float bias_s[225];
    __shared__ int   reg_s[NT];

    const float* base = qkv + (size_t)b_ * NT * QKVN;

    for (int i = tid; i < 512; i += 64) {
        int r = i >> 3, c4 = (i & 7) << 2;
        float4 kv = *(const float4*)(base + r * QKVN + 192 + h * HD + c4);
        float4 vv = *(const float4*)(base + r * QKVN + 384 + h * HD + c4);
        Ks[r][c4 + 0] = rtf32(kv.x); Ks[r][c4 + 1] = rtf32(kv.y);
        Ks[r][c4 + 2] = rtf32(kv.z); Ks[r][c4 + 3] = rtf32(kv.w);
        Vs[r][c4 + 0] = rtf32(vv.x); Vs[r][c4 + 1] = rtf32(vv.y);
        Vs[r][c4 + 2] = rtf32(vv.z); Vs[r][c4 + 3] = rtf32(vv.w);
    }
    for (int i = tid; i < 225; i += 64) bias_s[i] = rpb[i * NHEADS + h];
    {
        int wi = b_ % NWIN;
        int r = tid >> 3, c = tid & 7;
        int gh = (wi / 7) * 8 + r;
        int gw = (wi % 7) * 8 + c;
        reg_s[tid] = ((gh < 48) ? 0 : (gh < 52 ? 1 : 2)) * 3
                   + ((gw < 48) ? 0 : (gw < 52 ? 1 : 2));
    }
    __syncthreads();

    const int m0 = warp * 32;
    const int qr = lane >> 2, qk = lane & 3;

    uint32_t qa[4][2][4];
    #pragma unroll
    for (int ks = 0; ks < 4; ks++)
        #pragma unroll
        for (int mf = 0; mf < 2; mf++) {
            const float* qp = base + (size_t)(m0 + mf * 16 + qr) * QKVN + h * HD + ks * 8 + qk;
            qa[ks][mf][0] = __float_as_uint(rtf32(qp[0]            * SCALE_));
            qa[ks][mf][1] = __float_as_uint(rtf32(qp[8 * QKVN]     * SCALE_));
            qa[ks][mf][2] = __float_as_uint(rtf32(qp[4]            * SCALE_));
            qa[ks][mf][3] = __float_as_uint(rtf32(qp[8 * QKVN + 4] * SCALE_));
        }

    float sacc[2][8][4];
    #pragma unroll
    for (int mf = 0; mf < 2; mf++)
        #pragma unroll
        for (int nf = 0; nf < 8; nf++)
            #pragma unroll
            for (int e = 0; e < 4; e++) sacc[mf][nf][e] = 0.f;

    #pragma unroll
    for (int ks = 0; ks < 4; ks++) {
        uint32_t kb[8][2];
        #pragma unroll
        for (int nf = 0; nf < 8; nf++) {
            kb[nf][0] = __float_as_uint(Ks[nf * 8 + qr][ks * 8 + qk]);
            kb[nf][1] = __float_as_uint(Ks[nf * 8 + qr][ks * 8 + qk + 4]);
        }
        #pragma unroll
        for (int mf = 0; mf < 2; mf++)
            #pragma unroll
            for (int nf = 0; nf < 8; nf++)
                mma_tf32(sacc[mf][nf], qa[ks][mf], kb[nf]);
    }

    #pragma unroll
    for (int mf = 0; mf < 2; mf++) {
        #pragma unroll
        for (int half = 0; half < 2; half++) {
            int row = m0 + mf * 16 + qr + half * 8;
            int r1 = row >> 3, c1 = row & 7, myreg = reg_s[row];
            float mx = -1e30f;
            #pragma unroll
            for (int nf = 0; nf < 8; nf++)
                #pragma unroll
                for (int j = 0; j < 2; j++) {
                    int col = nf * 8 + qk * 2 + j;
                    float v = sacc[mf][nf][half * 2 + j]
                            + bias_s[(r1 - (col >> 3) + 7) * 15 + (c1 - (col & 7) + 7)];
                    if (reg_s[col] != myreg) v -= 100.f;
                    sacc[mf][nf][half * 2 + j] = v;
                    mx = fmaxf(mx, v);
                }
            mx = fmaxf(mx, __shfl_xor_sync(0xffffffffu, mx, 1));
            mx = fmaxf(mx, __shfl_xor_sync(0xffffffffu, mx, 2));
            float sum = 0.f;
            #pragma unroll
            for (int nf = 0; nf < 8; nf++)
                #pragma unroll
                for (int j = 0; j < 2; j++) {
                    float e = __expf(sacc[mf][nf][half * 2 + j] - mx);
                    sacc[mf][nf][half * 2 + j] = e;
                    sum += e;
                }
            sum += __shfl_xor_sync(0xffffffffu, sum, 1);
            sum += __shfl_xor_sync(0xffffffffu, sum, 2);
            float rinv = 1.f / sum;
            #pragma unroll
            for (int nf = 0; nf < 8; nf++)
                #pragma unroll
                for (int j = 0; j < 2; j++)
                    sacc[mf][nf][half * 2 + j] = rtf32(sacc[mf][nf][half * 2 + j] * rinv);
        }
    }

    float pacc[2][4][4];
    #pragma unroll
    for (int mf = 0; mf < 2; mf++)
        #pragma unroll
        for (int nf = 0; nf < 4; nf++)
            #pragma unroll
            for (int e = 0; e < 4; e++) pacc[mf][nf][e] = 0.f;

    const int c    = lane & 3;
    const int src0 = (lane & ~3) | (c >> 1);
    const int src1 = src0 + 2;
    const bool odd = c & 1;

    #pragma unroll
    for (int kc = 0; kc < 8; kc++) {
        uint32_t vb[4][2];
        #pragma unroll
        for (int nf = 0; nf < 4; nf++) {
            vb[nf][0] = __float_as_uint(Vs[kc * 8 + c]    [nf * 8 + qr]);
            vb[nf][1] = __float_as_uint(Vs[kc * 8 + c + 4][nf * 8 + qr]);
        }
        #pragma unroll
        for (int mf = 0; mf < 2; mf++) {
            float s0 = sacc[mf][kc][0], s1 = sacc[mf][kc][1];
            float s2 = sacc[mf][kc][2], s3 = sacc[mf][kc][3];
            float v00 = __shfl_sync(0xffffffffu, s0, src0);
            float v01 = __shfl_sync(0xffffffffu, s1, src0);
            float v20 = __shfl_sync(0xffffffffu, s2, src0);
            float v21 = __shfl_sync(0xffffffffu, s3, src0);
            float w00 = __shfl_sync(0xffffffffu, s0, src1);
            float w01 = __shfl_sync(0xffffffffu, s1, src1);
            float w20 = __shfl_sync(0xffffffffu, s2, src1);
            float w21 = __shfl_sync(0xffffffffu, s3, src1);
            uint32_t pa[4];
            pa[0] = __float_as_uint(odd ? v01 : v00);
            pa[1] = __float_as_uint(odd ? v21 : v20);
            pa[2] = __float_as_uint(odd ? w01 : w00);
            pa[3] = __float_as_uint(odd ? w21 : w20);
            #pragma unroll
            for (int nf = 0; nf < 4; nf++)
                mma_tf32(pacc[mf][nf], pa, vb[nf]);
        }
    }

    #pragma unroll
    for (int mf = 0; mf < 2; mf++) {
        int row = m0 + mf * 16 + qr;
        #pragma unroll
        for (int nf = 0; nf < 4; nf++) {
            int col = h * HD + nf * 8 + c * 2;
            float* o = out + (size_t)(b_ * NT + row) * CC + col;
            *(float2*)o = make_float2(rtf32(pacc[mf][nf][0]), rtf32(pacc[mf][nf][1]));
            *(float2*)(o + 8 * CC) = make_float2(rtf32(pacc[mf][nf][2]), rtf32(pacc[mf][nf][3]));
        }
    }
}

// ---------------- launch ----------------
extern "C" void kernel_launch(void* const* d_in, const int* in_sizes, int n_in,
                              void* d_out, int out_size)
{
    const float* x      = (const float*)d_in[0];
    const float* ln1_w  = (const float*)d_in[1];
    const float* ln1_b  = (const float*)d_in[2];
    const float* qkv_w  = (const float*)d_in[3];
    const float* qkv_b  = (const float*)d_in[4];
    const float* proj_w = (const float*)d_in[5];
    const float* proj_b = (const float*)d_in[6];
    const float* rpb    = (const float*)d_in[7];
    const float* ln2_w  = (const float*)d_in[8];
    const float* ln2_b  = (const float*)d_in[9];
    const float* fc1_w  = (const float*)d_in[10];
    const float* fc1_b  = (const float*)d_in[11];
    const float* fc2_w  = (const float*)d_in[12];
    const float* fc2_b  = (const float*)d_in[13];
    float* out = (float*)d_out;

    float *xw, *qkv, *attn, *xn2, *h1, *wr;
    cudaGetSymbolAddress((void**)&xw,   g_xw);
    cudaGetSymbolAddress((void**)&qkv,  g_qkv);
    cudaGetSymbolAddress((void**)&attn, g_attn);
    cudaGetSymbolAddress((void**)&xn2,  g_xn2);
    cudaGetSymbolAddress((void**)&h1,   g_h1);
    cudaGetSymbolAddress((void**)&wr,   g_wr);

    cudaFuncSetAttribute(gemm_tc<0>, cudaFuncAttributeMaxDynamicSharedMemorySize, SMEM_BYTES);
    cudaFuncSetAttribute(gemm_tc<1>, cudaFuncAttributeMaxDynamicSharedMemorySize, SMEM_BYTES);
    cudaFuncSetAttribute(gemm_tc<2>, cudaFuncAttributeMaxDynamicSharedMemorySize, SMEM_BYTES);
    cudaFuncSetAttribute(gemm_tc<3>, cudaFuncAttributeMaxDynamicSharedMemorySize, SMEM_BYTES);

    prep_w_kernel<<<(147456 + 255) / 256, 256>>>(qkv_w, proj_w, fc1_w, fc2_w);
    ln_kernel<true><<<MROWS, CC>>>(x, ln1_w, ln1_b, xw);
    gemm_tc<0><<<dim3(QKVN / BN, MROWS / BM), 256, SMEM_BYTES>>>(
        xw, wr + WOFF_QKV, qkv_b, nullptr, qkv, MROWS, QKVN, CC);
    attn_mma_kernel<<<dim3(BWIN, NHEADS), 64>>>(qkv, rpb, attn);
    gemm_tc<2><<<dim3(CC / BN, MROWS / BM), 256, SMEM_BYTES>>>(
        attn, wr + WOFF_PROJ, proj_b, x, out, MROWS, CC, CC);
    ln_kernel<false><<<MROWS, CC>>>(out, ln2_w, ln2_b, xn2);
    gemm_tc<1><<<dim3(HID / BN, MROWS / BM), 256, SMEM_BYTES>>>(
        xn2, wr + WOFF_FC1, fc1_b, nullptr, h1, MROWS, HID, CC);
    gemm_tc<3><<<dim3(CC / BN, MROWS / BM), 256, SMEM_BYTES>>>(
        h1, wr + WOFF_FC2, fc2_b, out, out, MROWS, CC, HID);
}

// round 6
// speedup vs baseline: 3.2611x; 1.2724x over previous
#include <cuda_runtime.h>
#include <cuda_bf16.h>
#include <math.h>
#include <stdint.h>

// ---------------- problem constants ----------------
#define BB     64
#define HH     56
#define WW_    56
#define CC     192
#define LL     (HH*WW_)            // 3136
#define MROWS  (BB*LL)             // 200704
#define NHEADS 6
#define HD     32
#define NT     64
#define NWIN   49
#define BWIN   (BB*NWIN)           // 3136
#define HID    768
#define QKVN   576
#define SCALE_ 0.17677669529663687f

// GEMM tiling (bf16 m16n8k16)
#define BM 256
#define BN 64
#define BK 32
#define LDA2 20     // uint32 row stride for A smem (16 data + 4 pad) -> conflict-free
#define LDB2 20
#define SMEM_BYTES ((2*BM*LDA2 + 2*BN*LDB2) * 4)   // 51200

// ---------------- scratch ----------------
__device__ __nv_bfloat16 g_xw  [(size_t)MROWS * CC];
__device__ __nv_bfloat16 g_qkv [(size_t)MROWS * QKVN];
__device__ __nv_bfloat16 g_attn[(size_t)MROWS * CC];
__device__ __nv_bfloat16 g_xn2 [(size_t)MROWS * CC];
__device__ __nv_bfloat16 g_h1  [(size_t)MROWS * HID];
__device__ __nv_bfloat16 g_wb  [110592 + 36864 + 147456 + 147456]; // transposed [N][K] bf16

#define WOFF_QKV  0
#define WOFF_PROJ 110592
#define WOFF_FC1  147456
#define WOFF_FC2  294912

__device__ __forceinline__ float rtf32(float x) {
    uint32_t u;
    asm("cvt.rna.tf32.f32 %0, %1;" : "=r"(u) : "f"(x));
    return __uint_as_float(u);
}
__device__ __forceinline__ uint32_t smem_u32(const void* p) {
    uint32_t a;
    asm("{.reg .u64 t; cvta.to.shared.u64 t, %1; cvt.u32.u64 %0, t;}" : "=r"(a) : "l"(p));
    return a;
}
__device__ __forceinline__ void cp_async16(uint32_t dst, const void* src) {
    asm volatile("cp.async.cg.shared.global [%0], [%1], 16;\n" :: "r"(dst), "l"(src));
}
__device__ __forceinline__ void mma_bf16(float* c, const uint32_t* a, const uint32_t* b) {
    asm volatile(
        "mma.sync.aligned.m16n8k16.row.col.f32.bf16.bf16.f32 "
        "{%0,%1,%2,%3}, {%4,%5,%6,%7}, {%8,%9}, {%0,%1,%2,%3};\n"
        : "+f"(c[0]), "+f"(c[1]), "+f"(c[2]), "+f"(c[3])
        : "r"(a[0]), "r"(a[1]), "r"(a[2]), "r"(a[3]), "r"(b[0]), "r"(b[1]));
}
__device__ __forceinline__ void mma_tf32(float* c, const uint32_t* a, const uint32_t* b) {
    asm volatile(
        "mma.sync.aligned.m16n8k8.row.col.f32.tf32.tf32.f32 "
        "{%0,%1,%2,%3}, {%4,%5,%6,%7}, {%8,%9}, {%0,%1,%2,%3};\n"
        : "+f"(c[0]), "+f"(c[1]), "+f"(c[2]), "+f"(c[3])
        : "r"(a[0]), "r"(a[1]), "r"(a[2]), "r"(a[3]), "r"(b[0]), "r"(b[1]));
}

__device__ __forceinline__ int win_to_global(int wrow) {
    int b_  = wrow >> 6;
    int n   = wrow & 63;
    int b   = b_ / NWIN;
    int wi  = b_ - b * NWIN;
    int hp  = (wi / 7) * 8 + (n >> 3);
    int wp  = (wi % 7) * 8 + (n & 7);
    int h = hp + 4; if (h >= HH)  h -= HH;
    int w = wp + 4; if (w >= WW_) w -= WW_;
    return b * LL + h * WW_ + w;
}

// ---------------- weight prep: convert to bf16 AND transpose to [N][K] ----------------
__global__ void prep_w_kernel(const float* __restrict__ qkv_w,
                              const float* __restrict__ proj_w,
                              const float* __restrict__ fc1_w,
                              const float* __restrict__ fc2_w)
{
    int i = blockIdx.x * 256 + threadIdx.x;
    if (i < 192 * 576) {
        int k = i / 576, n = i % 576;
        g_wb[WOFF_QKV + n * 192 + k] = __float2bfloat16_rn(qkv_w[i]);
    }
    if (i < 192 * 192) {
        int k = i / 192, n = i % 192;
        g_wb[WOFF_PROJ + n * 192 + k] = __float2bfloat16_rn(proj_w[i]);
    }
    if (i < 192 * 768) {
        int k = i / 768, n = i % 768;
        g_wb[WOFF_FC1 + n * 192 + k] = __float2bfloat16_rn(fc1_w[i]);
    }
    if (i < 768 * 192) {
        int k = i / 192, n = i % 192;
        g_wb[WOFF_FC2 + n * 768 + k] = __float2bfloat16_rn(fc2_w[i]);
    }
}

// ---------------- LayerNorm -> bf16 ----------------
template<bool MAP>
__global__ void ln_kernel(const float* __restrict__ x,
                          const float* __restrict__ w,
                          const float* __restrict__ b,
                          __nv_bfloat16* __restrict__ out)
{
    int row = blockIdx.x;
    int tid = threadIdx.x;
    int g = MAP ? win_to_global(row) : row;
    float v = x[(size_t)g * CC + tid];

    __shared__ float sh[12];
    float s = v, s2 = v * v;
    #pragma unroll
    for (int o = 16; o; o >>= 1) {
        s  += __shfl_xor_sync(0xffffffffu, s,  o);
        s2 += __shfl_xor_sync(0xffffffffu, s2, o);
    }
    int wp = tid >> 5;
    if ((tid & 31) == 0) { sh[wp] = s; sh[6 + wp] = s2; }
    __syncthreads();
    float ts = 0.f, ts2 = 0.f;
    #pragma unroll
    for (int i = 0; i < 6; i++) { ts += sh[i]; ts2 += sh[6 + i]; }
    const float inv = 1.f / 192.f;
    float mu  = ts * inv;
    float var = ts2 * inv - mu * mu;
    float rs  = rsqrtf(var + 1e-5f);
    out[(size_t)row * CC + tid] = __float2bfloat16_rn((v - mu) * rs * w[tid] + b[tid]);
}

// ---------------- bf16 tensor-core GEMM ----------------
// C[M,N] = A[M,K](bf16) @ Wt[N,K]^T(bf16) + bias, epilogues:
//   EPI 0: bf16 store          EPI 1: GELU -> bf16 store
//   EPI 2: fp32 scatter+res    EPI 3: fp32 residual in place
template<int EPI, typename OutT>
__global__ void __launch_bounds__(256)
gemm_bf(const __nv_bfloat16* __restrict__ A, const __nv_bfloat16* __restrict__ Wt,
        const float* __restrict__ bias, const float* __restrict__ res,
        OutT* __restrict__ Cout, int M, int N, int K)
{
    extern __shared__ uint32_t smem[];
    uint32_t* As = smem;                     // [2][BM][LDA2]
    uint32_t* Bs = smem + 2 * BM * LDA2;     // [2][BN][LDB2]

    const int tid  = threadIdx.x;
    const int wid  = tid >> 5, lane = tid & 31;
    const int bm   = blockIdx.y * BM, bn = blockIdx.x * BN;
    const int warp_m = (wid >> 1) * 64;
    const int warp_n = (wid & 1) * 32;
    const int lr = lane >> 2, lc = lane & 3;

    float acc[4][4][4];
    #pragma unroll
    for (int f = 0; f < 4; f++)
        #pragma unroll
        for (int g = 0; g < 4; g++)
            #pragma unroll
            for (int r = 0; r < 4; r++) acc[f][g][r] = 0.f;

    auto load_tiles = [&](int k0, int stage) {
        uint32_t* as = As + stage * (BM * LDA2);
        uint32_t* bs = Bs + stage * (BN * LDB2);
        #pragma unroll
        for (int i = 0; i < 4; i++) {
            int idx = tid + i * 256;            // 1024 chunks of 16B
            int r = idx >> 2, c = idx & 3;
            cp_async16(smem_u32(&as[r * LDA2 + c * 4]),
                       A + (size_t)(bm + r) * K + k0 + c * 8);
        }
        {
            int r = tid >> 2, c = tid & 3;       // 256 chunks
            cp_async16(smem_u32(&bs[r * LDB2 + c * 4]),
                       Wt + (size_t)(bn + r) * K + k0 + c * 8);
        }
        asm volatile("cp.async.commit_group;\n");
    };

    load_tiles(0, 0);
    asm volatile("cp.async.wait_group 0;\n");
    __syncthreads();

    const int KT = K >> 5;
    for (int kt = 0; kt < KT; kt++) {
        int stage = kt & 1;
        if (kt + 1 < KT) load_tiles((kt + 1) << 5, stage ^ 1);

        const uint32_t* as = As + stage * (BM * LDA2) + warp_m * LDA2;
        const uint32_t* bs = Bs + stage * (BN * LDB2) + warp_n * LDB2;

        #pragma unroll
        for (int ks = 0; ks < 2; ks++) {
            int ko = ks * 8 + lc;
            uint32_t a[4][4];
            #pragma unroll
            for (int f = 0; f < 4; f++) {
                const uint32_t* ap = as + (f * 16 + lr) * LDA2 + ko;
                a[f][0] = ap[0];
                a[f][1] = ap[8 * LDA2];
                a[f][2] = ap[4];
                a[f][3] = ap[8 * LDA2 + 4];
            }
            uint32_t b[4][2];
            #pragma unroll
            for (int g = 0; g < 4; g++) {
                const uint32_t* bp = bs + (g * 8 + lr) * LDB2 + ko;
                b[g][0] = bp[0];
                b[g][1] = bp[4];
            }
            #pragma unroll
            for (int f = 0; f < 4; f++)
                #pragma unroll
                for (int g = 0; g < 4; g++)
                    mma_bf16(acc[f][g], a[f], b[g]);
        }
        asm volatile("cp.async.wait_group 0;\n");
        __syncthreads();
    }

    // epilogue
    #pragma unroll
    for (int f = 0; f < 4; f++) {
        #pragma unroll
        for (int i = 0; i < 2; i++) {
            int m  = bm + warp_m + f * 16 + lr + i * 8;
            int gm = (EPI == 2) ? win_to_global(m) : m;
            #pragma unroll
            for (int g = 0; g < 4; g++) {
                int n = bn + warp_n + g * 8 + lc * 2;
                float v0 = acc[f][g][i * 2 + 0] + bias[n];
                float v1 = acc[f][g][i * 2 + 1] + bias[n + 1];
                if (EPI == 1) {
                    v0 = 0.5f * v0 * (1.f + erff(v0 * 0.70710678118654752f));
                    v1 = 0.5f * v1 * (1.f + erff(v1 * 0.70710678118654752f));
                }
                if (EPI == 0 || EPI == 1) {
                    *(__nv_bfloat162*)((__nv_bfloat16*)Cout + (size_t)m * N + n) =
                        __floats2bfloat162_rn(v0, v1);
                } else {
                    const float* rp = res + (size_t)((EPI == 2) ? gm : m) * N + n;
                    float2 r2 = *(const float2*)rp;
                    v0 += r2.x; v1 += r2.y;
                    *(float2*)((float*)Cout + (size_t)gm * N + n) = make_float2(v0, v1);
                }
            }
        }
    }
}

// ---------------- tensor-core windowed attention (bf16 in, bf16 out) ----------------
__global__ void __launch_bounds__(64)
attn_mma_kernel(const __nv_bfloat16* __restrict__ qkv, const float* __restrict__ rpb,
                __nv_bfloat16* __restrict__ out)
{
    const int b_   = blockIdx.x;
    const int h    = blockIdx.y;
    const int tid  = threadIdx.x;
    const int warp = tid >> 5, lane = tid & 31;

    __shared__ float Ks[NT][36];
    __shared__ float Vs[NT][40];
    __shared__ float bias_s[225];
    __shared__ int   reg_s[NT];

    const __nv_bfloat16* base = qkv + (size_t)b_ * NT * QKVN;

    for (int i = tid; i < 512; i += 64) {
        int r = i >> 3, c4 = (i & 7) << 2;
        const __nv_bfloat162* kp = (const __nv_bfloat162*)(base + r * QKVN + 192 + h * HD + c4);
        const __nv_bfloat162* vp = (const __nv_bfloat162*)(base + r * QKVN + 384 + h * HD + c4);
        float2 k0 = __bfloat1622float2(kp[0]);
        float2 k1 = __bfloat1622float2(kp[1]);
        float2 v0 = __bfloat1622float2(vp[0]);
        float2 v1 = __bfloat1622float2(vp[1]);
        Ks[r][c4 + 0] = k0.x; Ks[r][c4 + 1] = k0.y;
        Ks[r][c4 + 2] = k1.x; Ks[r][c4 + 3] = k1.y;
        Vs[r][c4 + 0] = v0.x; Vs[r][c4 + 1] = v0.y;
        Vs[r][c4 + 2] = v1.x; Vs[r][c4 + 3] = v1.y;
    }
    for (int i = tid; i < 225; i += 64) bias_s[i] = rpb[i * NHEADS + h];
    {
        int wi = b_ % NWIN;
        int r = tid >> 3, c = tid & 7;
        int gh = (wi / 7) * 8 + r;
        int gw = (wi % 7) * 8 + c;
        reg_s[tid] = ((gh < 48) ? 0 : (gh < 52 ? 1 : 2)) * 3
                   + ((gw < 48) ? 0 : (gw < 52 ? 1 : 2));
    }
    __syncthreads();

    const int m0 = warp * 32;
    const int qr = lane >> 2, qk = lane & 3;

    uint32_t qa[4][2][4];
    #pragma unroll
    for (int ks = 0; ks < 4; ks++)
        #pragma unroll
        for (int mf = 0; mf < 2; mf++) {
            const __nv_bfloat16* qp = base + (size_t)(m0 + mf * 16 + qr) * QKVN + h * HD + ks * 8 + qk;
            qa[ks][mf][0] = __float_as_uint(rtf32(__bfloat162float(qp[0])            * SCALE_));
            qa[ks][mf][1] = __float_as_uint(rtf32(__bfloat162float(qp[8 * QKVN])     * SCALE_));
            qa[ks][mf][2] = __float_as_uint(rtf32(__bfloat162float(qp[4])            * SCALE_));
            qa[ks][mf][3] = __float_as_uint(rtf32(__bfloat162float(qp[8 * QKVN + 4]) * SCALE_));
        }

    float sacc[2][8][4];
    #pragma unroll
    for (int mf = 0; mf < 2; mf++)
        #pragma unroll
        for (int nf = 0; nf < 8; nf++)
            #pragma unroll
            for (int e = 0; e < 4; e++) sacc[mf][nf][e] = 0.f;

    #pragma unroll
    for (int ks = 0; ks < 4; ks++) {
        uint32_t kb[8][2];
        #pragma unroll
        for (int nf = 0; nf < 8; nf++) {
            kb[nf][0] = __float_as_uint(Ks[nf * 8 + qr][ks * 8 + qk]);
            kb[nf][1] = __float_as_uint(Ks[nf * 8 + qr][ks * 8 + qk + 4]);
        }
        #pragma unroll
        for (int mf = 0; mf < 2; mf++)
            #pragma unroll
            for (int nf = 0; nf < 8; nf++)
                mma_tf32(sacc[mf][nf], qa[ks][mf], kb[nf]);
    }

    #pragma unroll
    for (int mf = 0; mf < 2; mf++) {
        #pragma unroll
        for (int half = 0; half < 2; half++) {
            int row = m0 + mf * 16 + qr + half * 8;
            int r1 = row >> 3, c1 = row & 7, myreg = reg_s[row];
            float mx = -1e30f;
            #pragma unroll
            for (int nf = 0; nf < 8; nf++)
                #pragma unroll
                for (int j = 0; j < 2; j++) {
                    int col = nf * 8 + qk * 2 + j;
                    float v = sacc[mf][nf][half * 2 + j]
                            + bias_s[(r1 - (col >> 3) + 7) * 15 + (c1 - (col & 7) + 7)];
                    if (reg_s[col] != myreg) v -= 100.f;
                    sacc[mf][nf][half * 2 + j] = v;
                    mx = fmaxf(mx, v);
                }
            mx = fmaxf(mx, __shfl_xor_sync(0xffffffffu, mx, 1));
            mx = fmaxf(mx, __shfl_xor_sync(0xffffffffu, mx, 2));
            float sum = 0.f;
            #pragma unroll
            for (int nf = 0; nf < 8; nf++)
                #pragma unroll
                for (int j = 0; j < 2; j++) {
                    float e = __expf(sacc[mf][nf][half * 2 + j] - mx);
                    sacc[mf][nf][half * 2 + j] = e;
                    sum += e;
                }
            sum += __shfl_xor_sync(0xffffffffu, sum, 1);
            sum += __shfl_xor_sync(0xffffffffu, sum, 2);
            float rinv = 1.f / sum;
            #pragma unroll
            for (int nf = 0; nf < 8; nf++)
                #pragma unroll
                for (int j = 0; j < 2; j++)
                    sacc[mf][nf][half * 2 + j] = rtf32(sacc[mf][nf][half * 2 + j] * rinv);
        }
    }

    float pacc[2][4][4];
    #pragma unroll
    for (int mf = 0; mf < 2; mf++)
        #pragma unroll
        for (int nf = 0; nf < 4; nf++)
            #pragma unroll
            for (int e = 0; e < 4; e++) pacc[mf][nf][e] = 0.f;

    const int c    = lane & 3;
    const int src0 = (lane & ~3) | (c >> 1);
    const int src1 = src0 + 2;
    const bool odd = c & 1;

    #pragma unroll
    for (int kc = 0; kc < 8; kc++) {
        uint32_t vb[4][2];
        #pragma unroll
        for (int nf = 0; nf < 4; nf++) {
            vb[nf][0] = __float_as_uint(Vs[kc * 8 + c]    [nf * 8 + qr]);
            vb[nf][1] = __float_as_uint(Vs[kc * 8 + c + 4][nf * 8 + qr]);
        }
        #pragma unroll
        for (int mf = 0; mf < 2; mf++) {
            float s0 = sacc[mf][kc][0], s1 = sacc[mf][kc][1];
            float s2 = sacc[mf][kc][2], s3 = sacc[mf][kc][3];
            float v00 = __shfl_sync(0xffffffffu, s0, src0);
            float v01 = __shfl_sync(0xffffffffu, s1, src0);
            float v20 = __shfl_sync(0xffffffffu, s2, src0);
            float v21 = __shfl_sync(0xffffffffu, s3, src0);
            float w00 = __shfl_sync(0xffffffffu, s0, src1);
            float w01 = __shfl_sync(0xffffffffu, s1, src1);
            float w20 = __shfl_sync(0xffffffffu, s2, src1);
            float w21 = __shfl_sync(0xffffffffu, s3, src1);
            uint32_t pa[4];
            pa[0] = __float_as_uint(odd ? v01 : v00);
            pa[1] = __float_as_uint(odd ? v21 : v20);
            pa[2] = __float_as_uint(odd ? w01 : w00);
            pa[3] = __float_as_uint(odd ? w21 : w20);
            #pragma unroll
            for (int nf = 0; nf < 4; nf++)
                mma_tf32(pacc[mf][nf], pa, vb[nf]);
        }
    }

    #pragma unroll
    for (int mf = 0; mf < 2; mf++) {
        int row = m0 + mf * 16 + qr;
        #pragma unroll
        for (int nf = 0; nf < 4; nf++) {
            int col = h * HD + nf * 8 + c * 2;
            __nv_bfloat16* o = out + (size_t)(b_ * NT + row) * CC + col;
            *(__nv_bfloat162*)o = __floats2bfloat162_rn(pacc[mf][nf][0], pacc[mf][nf][1]);
            *(__nv_bfloat162*)(o + 8 * CC) = __floats2bfloat162_rn(pacc[mf][nf][2], pacc[mf][nf][3]);
        }
    }
}

// ---------------- launch ----------------
extern "C" void kernel_launch(void* const* d_in, const int* in_sizes, int n_in,
                              void* d_out, int out_size)
{
    const float* x      = (const float*)d_in[0];
    const float* ln1_w  = (const float*)d_in[1];
    const float* ln1_b  = (const float*)d_in[2];
    const float* qkv_w  = (const float*)d_in[3];
    const float* qkv_b  = (const float*)d_in[4];
    const float* proj_w = (const float*)d_in[5];
    const float* proj_b = (const float*)d_in[6];
    const float* rpb    = (const float*)d_in[7];
    const float* ln2_w  = (const float*)d_in[8];
    const float* ln2_b  = (const float*)d_in[9];
    const float* fc1_w  = (const float*)d_in[10];
    const float* fc1_b  = (const float*)d_in[11];
    const float* fc2_w  = (const float*)d_in[12];
    const float* fc2_b  = (const float*)d_in[13];
    float* out = (float*)d_out;

    __nv_bfloat16 *xw, *qkv, *attn, *xn2, *h1, *wb;
    cudaGetSymbolAddress((void**)&xw,   g_xw);
    cudaGetSymbolAddress((void**)&qkv,  g_qkv);
    cudaGetSymbolAddress((void**)&attn, g_attn);
    cudaGetSymbolAddress((void**)&xn2,  g_xn2);
    cudaGetSymbolAddress((void**)&h1,   g_h1);
    cudaGetSymbolAddress((void**)&wb,   g_wb);

    cudaFuncSetAttribute((const void*)gemm_bf<0, __nv_bfloat16>,
                         cudaFuncAttributeMaxDynamicSharedMemorySize, SMEM_BYTES);
    cudaFuncSetAttribute((const void*)gemm_bf<1, __nv_bfloat16>,
                         cudaFuncAttributeMaxDynamicSharedMemorySize, SMEM_BYTES);
    cudaFuncSetAttribute((const void*)gemm_bf<2, float>,
                         cudaFuncAttributeMaxDynamicSharedMemorySize, SMEM_BYTES);
    cudaFuncSetAttribute((const void*)gemm_bf<3, float>,
                         cudaFuncAttributeMaxDynamicSharedMemorySize, SMEM_BYTES);

    // 0. weights -> bf16, transposed [N][K]
    prep_w_kernel<<<(147456 + 255) / 256, 256>>>(qkv_w, proj_w, fc1_w, fc2_w);
    // 1. LN1 + shift + partition -> bf16
    ln_kernel<true><<<MROWS, CC>>>(x, ln1_w, ln1_b, xw);
    // 2. qkv (bf16 out)
    gemm_bf<0, __nv_bfloat16><<<dim3(QKVN / BN, MROWS / BM), 256, SMEM_BYTES>>>(
        xw, wb + WOFF_QKV, qkv_b, nullptr, qkv, MROWS, QKVN, CC);
    // 3. attention (bf16 in/out)
    attn_mma_kernel<<<dim3(BWIN, NHEADS), 64>>>(qkv, rpb, attn);
    // 4. proj + reverse + residual -> d_out fp32
    gemm_bf<2, float><<<dim3(CC / BN, MROWS / BM), 256, SMEM_BYTES>>>(
        attn, wb + WOFF_PROJ, proj_b, x, out, MROWS, CC, CC);
    // 5. LN2 -> bf16
    ln_kernel<false><<<MROWS, CC>>>(out, ln2_w, ln2_b, xn2);
    // 6. fc1 + GELU -> bf16
    gemm_bf<1, __nv_bfloat16><<<dim3(HID / BN, MROWS / BM), 256, SMEM_BYTES>>>(
        xn2, wb + WOFF_FC1, fc1_b, nullptr, h1, MROWS, HID, CC);
    // 7. fc2 + residual (in place on d_out)
    gemm_bf<3, float><<<dim3(CC / BN, MROWS / BM), 256, SMEM_BYTES>>>(
        h1, wb + WOFF_FC2, fc2_b, out, out, MROWS, CC, HID);
}

// round 8
// speedup vs baseline: 3.4242x; 1.0500x over previous
#include <cuda_runtime.h>
#include <cuda_bf16.h>
#include <math.h>
#include <stdint.h>

// ---------------- problem constants ----------------
#define BB     64
#define HH     56
#define WW_    56
#define CC     192
#define LL     (HH*WW_)            // 3136
#define MROWS  (BB*LL)             // 200704
#define NHEADS 6
#define HD     32
#define NT     64
#define NWIN   49
#define BWIN   (BB*NWIN)           // 3136
#define HID    768
#define QKVN   576
#define SCALE_ 0.17677669529663687f

// GEMM tiling (bf16 m16n8k16)
#define BM 256
#define BN 64
#define BK 32
#define LDA2 20     // uint32 row stride for A smem (16 data + 4 pad) -> conflict-free
#define LDB2 20
#define SMEM_BYTES ((2*BM*LDA2 + 2*BN*LDB2) * 4)   // 51200

// ---------------- scratch ----------------
__device__ __nv_bfloat16 g_xw  [(size_t)MROWS * CC];
__device__ __nv_bfloat16 g_qkv [(size_t)MROWS * QKVN];
__device__ __nv_bfloat16 g_attn[(size_t)MROWS * CC];
__device__ __nv_bfloat16 g_xn2 [(size_t)MROWS * CC];
__device__ __nv_bfloat16 g_h1  [(size_t)MROWS * HID];
__device__ __nv_bfloat16 g_wb  [110592 + 36864 + 147456 + 147456]; // transposed [N][K] bf16

#define WOFF_QKV  0
#define WOFF_PROJ 110592
#define WOFF_FC1  147456
#define WOFF_FC2  294912

__device__ __forceinline__ float rtf32(float x) {
    uint32_t u;
    asm("cvt.rna.tf32.f32 %0, %1;" : "=r"(u) : "f"(x));
    return __uint_as_float(u);
}
__device__ __forceinline__ uint32_t smem_u32(const void* p) {
    uint32_t a;
    asm("{.reg .u64 t; cvta.to.shared.u64 t, %1; cvt.u32.u64 %0, t;}" : "=r"(a) : "l"(p));
    return a;
}
__device__ __forceinline__ void cp_async16(uint32_t dst, const void* src) {
    asm volatile("cp.async.cg.shared.global [%0], [%1], 16;\n" :: "r"(dst), "l"(src));
}
__device__ __forceinline__ void ldsm_x4(uint32_t* r, uint32_t addr) {
    asm volatile("ldmatrix.sync.aligned.m8n8.x4.shared.b16 {%0,%1,%2,%3}, [%4];"
                 : "=r"(r[0]), "=r"(r[1]), "=r"(r[2]), "=r"(r[3]) : "r"(addr));
}
__device__ __forceinline__ void mma_bf16(float* c, const uint32_t* a, const uint32_t* b) {
    asm volatile(
        "mma.sync.aligned.m16n8k16.row.col.f32.bf16.bf16.f32 "
        "{%0,%1,%2,%3}, {%4,%5,%6,%7}, {%8,%9}, {%0,%1,%2,%3};\n"
        : "+f"(c[0]), "+f"(c[1]), "+f"(c[2]), "+f"(c[3])
        : "r"(a[0]), "r"(a[1]), "r"(a[2]), "r"(a[3]), "r"(b[0]), "r"(b[1]));
}
__device__ __forceinline__ void mma_tf32(float* c, const uint32_t* a, const uint32_t* b) {
    asm volatile(
        "mma.sync.aligned.m16n8k8.row.col.f32.tf32.tf32.f32 "
        "{%0,%1,%2,%3}, {%4,%5,%6,%7}, {%8,%9}, {%0,%1,%2,%3};\n"
        : "+f"(c[0]), "+f"(c[1]), "+f"(c[2]), "+f"(c[3])
        : "r"(a[0]), "r"(a[1]), "r"(a[2]), "r"(a[3]), "r"(b[0]), "r"(b[1]));
}

__device__ __forceinline__ int win_to_global(int wrow) {
    int b_  = wrow >> 6;
    int n   = wrow & 63;
    int b   = b_ / NWIN;
    int wi  = b_ - b * NWIN;
    int hp  = (wi / 7) * 8 + (n >> 3);
    int wp  = (wi % 7) * 8 + (n & 7);
    int h = hp + 4; if (h >= HH)  h -= HH;
    int w = wp + 4; if (w >= WW_) w -= WW_;
    return b * LL + h * WW_ + w;
}

// ---------------- weight prep: convert to bf16 AND transpose to [N][K] ----------------
__global__ void prep_w_kernel(const float* __restrict__ qkv_w,
                              const float* __restrict__ proj_w,
                              const float* __restrict__ fc1_w,
                              const float* __restrict__ fc2_w)
{
    int i = blockIdx.x * 256 + threadIdx.x;
    if (i < 192 * 576) {
        int k = i / 576, n = i % 576;
        g_wb[WOFF_QKV + n * 192 + k] = __float2bfloat16_rn(qkv_w[i]);
    }
    if (i < 192 * 192) {
        int k = i / 192, n = i % 192;
        g_wb[WOFF_PROJ + n * 192 + k] = __float2bfloat16_rn(proj_w[i]);
    }
    if (i < 192 * 768) {
        int k = i / 768, n = i % 768;
        g_wb[WOFF_FC1 + n * 192 + k] = __float2bfloat16_rn(fc1_w[i]);
    }
    if (i < 768 * 192) {
        int k = i / 192, n = i % 192;
        g_wb[WOFF_FC2 + n * 768 + k] = __float2bfloat16_rn(fc2_w[i]);
    }
}

// ---------------- LayerNorm -> bf16 ----------------
template<bool MAP>
__global__ void ln_kernel(const float* __restrict__ x,
                          const float* __restrict__ w,
                          const float* __restrict__ b,
                          __nv_bfloat16* __restrict__ out)
{
    int row = blockIdx.x;
    int tid = threadIdx.x;
    int g = MAP ? win_to_global(row) : row;
    float v = x[(size_t)g * CC + tid];

    __shared__ float sh[12];
    float s = v, s2 = v * v;
    #pragma unroll
    for (int o = 16; o; o >>= 1) {
        s  += __shfl_xor_sync(0xffffffffu, s,  o);
        s2 += __shfl_xor_sync(0xffffffffu, s2, o);
    }
    int wp = tid >> 5;
    if ((tid & 31) == 0) { sh[wp] = s; sh[6 + wp] = s2; }
    __syncthreads();
    float ts = 0.f, ts2 = 0.f;
    #pragma unroll
    for (int i = 0; i < 6; i++) { ts += sh[i]; ts2 += sh[6 + i]; }
    const float inv = 1.f / 192.f;
    float mu  = ts * inv;
    float var = ts2 * inv - mu * mu;
    float rs  = rsqrtf(var + 1e-5f);
    out[(size_t)row * CC + tid] = __float2bfloat16_rn((v - mu) * rs * w[tid] + b[tid]);
}

// ---------------- bf16 tensor-core GEMM with ldmatrix fragment loads ----------------
// C[M,N] = A[M,K](bf16) @ Wt[N,K]^T(bf16) + bias
//   EPI 0: bf16 store          EPI 1: GELU -> bf16 store
//   EPI 2: fp32 scatter+res    EPI 3: fp32 residual in place
template<int EPI, typename OutT>
__global__ void __launch_bounds__(256)
gemm_bf(const __nv_bfloat16* __restrict__ A, const __nv_bfloat16* __restrict__ Wt,
        const float* __restrict__ bias, const float* __restrict__ res,
        OutT* __restrict__ Cout, int M, int N, int K)
{
    extern __shared__ uint32_t smem[];
    uint32_t* As = smem;                     // [2][BM][LDA2]
    uint32_t* Bs = smem + 2 * BM * LDA2;     // [2][BN][LDB2]

    const int tid  = threadIdx.x;
    const int wid  = tid >> 5, lane = tid & 31;
    const int bm   = blockIdx.y * BM, bn = blockIdx.x * BN;
    const int warp_m = (wid >> 1) * 64;
    const int warp_n = (wid & 1) * 32;
    const int lr = lane >> 2, lc = lane & 3;

    float acc[4][4][4];
    #pragma unroll
    for (int f = 0; f < 4; f++)
        #pragma unroll
        for (int g = 0; g < 4; g++)
            #pragma unroll
            for (int r = 0; r < 4; r++) acc[f][g][r] = 0.f;

    auto load_tiles = [&](int k0, int stage) {
        uint32_t* as = As + stage * (BM * LDA2);
        uint32_t* bs = Bs + stage * (BN * LDB2);
        #pragma unroll
        for (int i = 0; i < 4; i++) {
            int idx = tid + i * 256;            // 1024 chunks of 16B
            int r = idx >> 2, c = idx & 3;
            cp_async16(smem_u32(&as[r * LDA2 + c * 4]),
                       A + (size_t)(bm + r) * K + k0 + c * 8);
        }
        {
            int r = tid >> 2, c = tid & 3;       // 256 chunks
            cp_async16(smem_u32(&bs[r * LDB2 + c * 4]),
                       Wt + (size_t)(bn + r) * K + k0 + c * 8);
        }
        asm volatile("cp.async.commit_group;\n");
    };

    // ldmatrix lane->address mapping (offsets in uint32 units)
    const int g8 = lane >> 3;
    const int a_row = (lane & 7) + ((g8 & 1) << 3);   // +8 rows for a1/a3
    const int a_k   = (g8 >> 1) << 2;                 // +4 words for a2/a3
    const int b_row = (lane & 7) + ((lane & 16) ? 8 : 0);  // +8 rows = next n8 tile
    const int b_k   = (lane & 8) ? 4 : 0;                  // +4 words = k-high half

    uint32_t aBase[2], bBase[2];
    #pragma unroll
    for (int st = 0; st < 2; st++) {
        aBase[st] = smem_u32(As + st * (BM * LDA2) + (warp_m + a_row) * LDA2 + a_k);
        bBase[st] = smem_u32(Bs + st * (BN * LDB2) + (warp_n + b_row) * LDB2 + b_k);
    }

    load_tiles(0, 0);
    asm volatile("cp.async.wait_group 0;\n");
    __syncthreads();

    const int KT = K >> 5;
    for (int kt = 0; kt < KT; kt++) {
        int stage = kt & 1;
        if (kt + 1 < KT) load_tiles((kt + 1) << 5, stage ^ 1);

        #pragma unroll
        for (int ks = 0; ks < 2; ks++) {
            uint32_t a[4][4];
            #pragma unroll
            for (int f = 0; f < 4; f++)
                ldsm_x4(a[f], aBase[stage] + (uint32_t)((f * 16 * LDA2 + ks * 8) * 4));
            uint32_t b[4][2];
            #pragma unroll
            for (int gp = 0; gp < 2; gp++) {
                uint32_t r[4];
                ldsm_x4(r, bBase[stage] + (uint32_t)((gp * 16 * LDB2 + ks * 8) * 4));
                b[gp * 2 + 0][0] = r[0]; b[gp * 2 + 0][1] = r[1];
                b[gp * 2 + 1][0] = r[2]; b[gp * 2 + 1][1] = r[3];
            }
            #pragma unroll
            for (int f = 0; f < 4; f++)
                #pragma unroll
                for (int g = 0; g < 4; g++)
                    mma_bf16(acc[f][g], a[f], b[g]);
        }
        asm volatile("cp.async.wait_group 0;\n");
        __syncthreads();
    }

    // epilogue
    #pragma unroll
    for (int f = 0; f < 4; f++) {
        #pragma unroll
        for (int i = 0; i < 2; i++) {
            int m  = bm + warp_m + f * 16 + lr + i * 8;
            int gm = (EPI == 2) ? win_to_global(m) : m;
            #pragma unroll
            for (int g = 0; g < 4; g++) {
                int n = bn + warp_n + g * 8 + lc * 2;
                float v0 = acc[f][g][i * 2 + 0] + bias[n];
                float v1 = acc[f][g][i * 2 + 1] + bias[n + 1];
                if (EPI == 1) {
                    v0 = 0.5f * v0 * (1.f + erff(v0 * 0.70710678118654752f));
                    v1 = 0.5f * v1 * (1.f + erff(v1 * 0.70710678118654752f));
                }
                if (EPI == 0 || EPI == 1) {
                    *(__nv_bfloat162*)((__nv_bfloat16*)Cout + (size_t)m * N + n) =
                        __floats2bfloat162_rn(v0, v1);
                } else {
                    const float* rp = res + (size_t)((EPI == 2) ? gm : m) * N + n;
                    float2 r2 = *(const float2*)rp;
                    v0 += r2.x; v1 += r2.y;
                    *(float2*)((float*)Cout + (size_t)gm * N + n) = make_float2(v0, v1);
                }
            }
        }
    }
}

// ---------------- tensor-core windowed attention (bf16 in, bf16 out) ----------------
__global__ void __launch_bounds__(64)
attn_mma_kernel(const __nv_bfloat16* __restrict__ qkv, const float* __restrict__ rpb,
                __nv_bfloat16* __restrict__ out)
{
    const int b_   = blockIdx.x;
    const int h    = blockIdx.y;
    const int tid  = threadIdx.x;
    const int warp = tid >> 5, lane = tid & 31;

    __shared__ float Ks[NT][36];
    __shared__ float Vs[NT][40];
    __shared__ float bias_s[225];
    __shared__ int   reg_s[NT];

    const __nv_bfloat16* base = qkv + (size_t)b_ * NT * QKVN;

    for (int i = tid; i < 512; i += 64) {
        int r = i >> 3, c4 = (i & 7) << 2;
        const __nv_bfloat162* kp = (const __nv_bfloat162*)(base + r * QKVN + 192 + h * HD + c4);
        const __nv_bfloat162* vp = (const __nv_bfloat162*)(base + r * QKVN + 384 + h * HD + c4);
        float2 k0 = __bfloat1622float2(kp[0]);
        float2 k1 = __bfloat1622float2(kp[1]);
        float2 v0 = __bfloat1622float2(vp[0]);
        float2 v1 = __bfloat1622float2(vp[1]);
        Ks[r][c4 + 0] = k0.x; Ks[r][c4 + 1] = k0.y;
        Ks[r][c4 + 2] = k1.x; Ks[r][c4 + 3] = k1.y;
        Vs[r][c4 + 0] = v0.x; Vs[r][c4 + 1] = v0.y;
        Vs[r][c4 + 2] = v1.x; Vs[r][c4 + 3] = v1.y;
    }
    for (int i = tid; i < 225; i += 64) bias_s[i] = rpb[i * NHEADS + h];
    {
        int wi = b_ % NWIN;
        int r = tid >> 3, c = tid & 7;
        int gh = (wi / 7) * 8 + r;
        int gw = (wi % 7) * 8 + c;
        reg_s[tid] = ((gh < 48) ? 0 : (gh < 52 ? 1 : 2)) * 3
                   + ((gw < 48) ? 0 : (gw < 52 ? 1 : 2));
    }
    __syncthreads();

    const int m0 = warp * 32;
    const int qr = lane >> 2, qk = lane & 3;

    uint32_t qa[4][2][4];
    #pragma unroll
    for (int ks = 0; ks < 4; ks++)
        #pragma unroll
        for (int mf = 0; mf < 2; mf++) {
            const __nv_bfloat16* qp = base + (size_t)(m0 + mf * 16 + qr) * QKVN + h * HD + ks * 8 + qk;
            qa[ks][mf][0] = __float_as_uint(rtf32(__bfloat162float(qp[0])            * SCALE_));
            qa[ks][mf][1] = __float_as_uint(rtf32(__bfloat162float(qp[8 * QKVN])     * SCALE_));
            qa[ks][mf][2] = __float_as_uint(rtf32(__bfloat162float(qp[4])            * SCALE_));
            qa[ks][mf][3] = __float_as_uint(rtf32(__bfloat162float(qp[8 * QKVN + 4]) * SCALE_));
        }

    float sacc[2][8][4];
    #pragma unroll
    for (int mf = 0; mf < 2; mf++)
        #pragma unroll
        for (int nf = 0; nf < 8; nf++)
            #pragma unroll
            for (int e = 0; e < 4; e++) sacc[mf][nf][e] = 0.f;

    #pragma unroll
    for (int ks = 0; ks < 4; ks++) {
        uint32_t kb[8][2];
        #pragma unroll
        for (int nf = 0; nf < 8; nf++) {
            kb[nf][0] = __float_as_uint(Ks[nf * 8 + qr][ks * 8 + qk]);
            kb[nf][1] = __float_as_uint(Ks[nf * 8 + qr][ks * 8 + qk + 4]);
        }
        #pragma unroll
        for (int mf = 0; mf < 2; mf++)
            #pragma unroll
            for (int nf = 0; nf < 8; nf++)
                mma_tf32(sacc[mf][nf], qa[ks][mf], kb[nf]);
    }

    #pragma unroll
    for (int mf = 0; mf < 2; mf++) {
        #pragma unroll
        for (int half = 0; half < 2; half++) {
            int row = m0 + mf * 16 + qr + half * 8;
            int r1 = row >> 3, c1 = row & 7, myreg = reg_s[row];
            float mx = -1e30f;
            #pragma unroll
            for (int nf = 0; nf < 8; nf++)
                #pragma unroll
                for (int j = 0; j < 2; j++) {
                    int col = nf * 8 + qk * 2 + j;
                    float v = sacc[mf][nf][half * 2 + j]
                            + bias_s[(r1 - (col >> 3) + 7) * 15 + (c1 - (col & 7) + 7)];
                    if (reg_s[col] != myreg) v -= 100.f;
                    sacc[mf][nf][half * 2 + j] = v;
                    mx = fmaxf(mx, v);
                }
            mx = fmaxf(mx, __shfl_xor_sync(0xffffffffu, mx, 1));
            mx = fmaxf(mx, __shfl_xor_sync(0xffffffffu, mx, 2));
            float sum = 0.f;
            #pragma unroll
            for (int nf = 0; nf < 8; nf++)
                #pragma unroll
                for (int j = 0; j < 2; j++) {
                    float e = __expf(sacc[mf][nf][half * 2 + j] - mx);
                    sacc[mf][nf][half * 2 + j] = e;
                    sum += e;
                }
            sum += __shfl_xor_sync(0xffffffffu, sum, 1);
            sum += __shfl_xor_sync(0xffffffffu, sum, 2);
            float rinv = 1.f / sum;
            #pragma unroll
            for (int nf = 0; nf < 8; nf++)
                #pragma unroll
                for (int j = 0; j < 2; j++)
                    sacc[mf][nf][half * 2 + j] = rtf32(sacc[mf][nf][half * 2 + j] * rinv);
        }
    }

    float pacc[2][4][4];
    #pragma unroll
    for (int mf = 0; mf < 2; mf++)
        #pragma unroll
        for (int nf = 0; nf < 4; nf++)
            #pragma unroll
            for (int e = 0; e < 4; e++) pacc[mf][nf][e] = 0.f;

    const int c    = lane & 3;
    const int src0 = (lane & ~3) | (c >> 1);
    const int src1 = src0 + 2;
    const bool odd = c & 1;

    #pragma unroll
    for (int kc = 0; kc < 8; kc++) {
        uint32_t vb[4][2];
        #pragma unroll
        for (int nf = 0; nf < 4; nf++) {
            vb[nf][0] = __float_as_uint(Vs[kc * 8 + c]    [nf * 8 + qr]);
            vb[nf][1] = __float_as_uint(Vs[kc * 8 + c + 4][nf * 8 + qr]);
        }
        #pragma unroll
        for (int mf = 0; mf < 2; mf++) {
            float s0 = sacc[mf][kc][0], s1 = sacc[mf][kc][1];
            float s2 = sacc[mf][kc][2], s3 = sacc[mf][kc][3];
            float v00 = __shfl_sync(0xffffffffu, s0, src0);
            float v01 = __shfl_sync(0xffffffffu, s1, src0);
            float v20 = __shfl_sync(0xffffffffu, s2, src0);
            float v21 = __shfl_sync(0xffffffffu, s3, src0);
            float w00 = __shfl_sync(0xffffffffu, s0, src1);
            float w01 = __shfl_sync(0xffffffffu, s1, src1);
            float w20 = __shfl_sync(0xffffffffu, s2, src1);
            float w21 = __shfl_sync(0xffffffffu, s3, src1);
            uint32_t pa[4];
            pa[0] = __float_as_uint(odd ? v01 : v00);
            pa[1] = __float_as_uint(odd ? v21 : v20);
            pa[2] = __float_as_uint(odd ? w01 : w00);
            pa[3] = __float_as_uint(odd ? w21 : w20);
            #pragma unroll
            for (int nf = 0; nf < 4; nf++)
                mma_tf32(pacc[mf][nf], pa, vb[nf]);
        }
    }

    #pragma unroll
    for (int mf = 0; mf < 2; mf++) {
        int row = m0 + mf * 16 + qr;
        #pragma unroll
        for (int nf = 0; nf < 4; nf++) {
            int col = h * HD + nf * 8 + c * 2;
            __nv_bfloat16* o = out + (size_t)(b_ * NT + row) * CC + col;
            *(__nv_bfloat162*)o = __floats2bfloat162_rn(pacc[mf][nf][0], pacc[mf][nf][1]);
            *(__nv_bfloat162*)(o + 8 * CC) = __floats2bfloat162_rn(pacc[mf][nf][2], pacc[mf][nf][3]);
        }
    }
}

// ---------------- launch ----------------
extern "C" void kernel_launch(void* const* d_in, const int* in_sizes, int n_in,
                              void* d_out, int out_size)
{
    const float* x      = (const float*)d_in[0];
    const float* ln1_w  = (const float*)d_in[1];
    const float* ln1_b  = (const float*)d_in[2];
    const float* qkv_w  = (const float*)d_in[3];
    const float* qkv_b  = (const float*)d_in[4];
    const float* proj_w = (const float*)d_in[5];
    const float* proj_b = (const float*)d_in[6];
    const float* rpb    = (const float*)d_in[7];
    const float* ln2_w  = (const float*)d_in[8];
    const float* ln2_b  = (const float*)d_in[9];
    const float* fc1_w  = (const float*)d_in[10];
    const float* fc1_b  = (const float*)d_in[11];
    const float* fc2_w  = (const float*)d_in[12];
    const float* fc2_b  = (const float*)d_in[13];
    float* out = (float*)d_out;

    __nv_bfloat16 *xw, *qkv, *attn, *xn2, *h1, *wb;
    cudaGetSymbolAddress((void**)&xw,   g_xw);
    cudaGetSymbolAddress((void**)&qkv,  g_qkv);
    cudaGetSymbolAddress((void**)&attn, g_attn);
    cudaGetSymbolAddress((void**)&xn2,  g_xn2);
    cudaGetSymbolAddress((void**)&h1,   g_h1);
    cudaGetSymbolAddress((void**)&wb,   g_wb);

    cudaFuncSetAttribute(gemm_bf<0, __nv_bfloat16>,
                         cudaFuncAttributeMaxDynamicSharedMemorySize, SMEM_BYTES);
    cudaFuncSetAttribute(gemm_bf<1, __nv_bfloat16>,
                         cudaFuncAttributeMaxDynamicSharedMemorySize, SMEM_BYTES);
    cudaFuncSetAttribute(gemm_bf<2, float>,
                         cudaFuncAttributeMaxDynamicSharedMemorySize, SMEM_BYTES);
    cudaFuncSetAttribute(gemm_bf<3, float>,
                         cudaFuncAttributeMaxDynamicSharedMemorySize, SMEM_BYTES);

    prep_w_kernel<<<(147456 + 255) / 256, 256>>>(qkv_w, proj_w, fc1_w, fc2_w);
    ln_kernel<true><<<MROWS, CC>>>(x, ln1_w, ln1_b, xw);
    gemm_bf<0, __nv_bfloat16><<<dim3(QKVN / BN, MROWS / BM), 256, SMEM_BYTES>>>(
        xw, wb + WOFF_QKV, qkv_b, nullptr, qkv, MROWS, QKVN, CC);
    attn_mma_kernel<<<dim3(BWIN, NHEADS), 64>>>(qkv, rpb, attn);
    gemm_bf<2, float><<<dim3(CC / BN, MROWS / BM), 256, SMEM_BYTES>>>(
        attn, wb + WOFF_PROJ, proj_b, x, out, MROWS, CC, CC);
    ln_kernel<false><<<MROWS, CC>>>(out, ln2_w, ln2_b, xn2);
    gemm_bf<1, __nv_bfloat16><<<dim3(HID / BN, MROWS / BM), 256, SMEM_BYTES>>>(
        xn2, wb + WOFF_FC1, fc1_b, nullptr, h1, MROWS, HID, CC);
    gemm_bf<3, float><<<dim3(CC / BN, MROWS / BM), 256, SMEM_BYTES>>>(
        h1, wb + WOFF_FC2, fc2_b, out, out, MROWS, CC, HID);
}

// round 14
// speedup vs baseline: 3.4358x; 1.0034x over previous
#include <cuda_runtime.h>
#include <cuda_bf16.h>
#include <math.h>
#include <stdint.h>

// ---------------- problem constants ----------------
#define BB     64
#define HH     56
#define WW_    56
#define CC     192
#define LL     (HH*WW_)            // 3136
#define MROWS  (BB*LL)             // 200704
#define NHEADS 6
#define HD     32
#define NT     64
#define NWIN   49
#define BWIN   (BB*NWIN)           // 3136
#define HID    768
#define QKVN   576
#define SCALE_ 0.17677669529663687f

// GEMM tiling (bf16 m16n8k16), 2-stage pipeline (known-good R8)
#define BM 256
#define BN 64
#define BK 32
#define LDA2 20     // uint32 row stride (16 data + 4 pad) -> conflict-free
#define LDB2 20
#define SMEM_BYTES ((2*BM*LDA2 + 2*BN*LDB2) * 4)   // 51200

// ---------------- scratch ----------------
__device__ __nv_bfloat16 g_xw  [(size_t)MROWS * CC];
__device__ __nv_bfloat16 g_qkv [(size_t)MROWS * QKVN];
__device__ __nv_bfloat16 g_attn[(size_t)MROWS * CC];
__device__ __nv_bfloat16 g_xn2 [(size_t)MROWS * CC];
__device__ __nv_bfloat16 g_h1  [(size_t)MROWS * HID];
__device__ __nv_bfloat16 g_wb  [110592 + 36864 + 147456 + 147456]; // transposed [N][K] bf16

#define WOFF_QKV  0
#define WOFF_PROJ 110592
#define WOFF_FC1  147456
#define WOFF_FC2  294912

__device__ __forceinline__ uint32_t smem_u32(const void* p) {
    uint32_t a;
    asm("{.reg .u64 t; cvta.to.shared.u64 t, %1; cvt.u32.u64 %0, t;}" : "=r"(a) : "l"(p));
    return a;
}
__device__ __forceinline__ void cp_async16(uint32_t dst, const void* src) {
    asm volatile("cp.async.cg.shared.global [%0], [%1], 16;\n" :: "r"(dst), "l"(src));
}
__device__ __forceinline__ void ldsm_x4(uint32_t* r, uint32_t addr) {
    asm volatile("ldmatrix.sync.aligned.m8n8.x4.shared.b16 {%0,%1,%2,%3}, [%4];"
                 : "=r"(r[0]), "=r"(r[1]), "=r"(r[2]), "=r"(r[3]) : "r"(addr));
}
__device__ __forceinline__ void mma_bf16(float* c, const uint32_t* a, const uint32_t* b) {
    asm volatile(
        "mma.sync.aligned.m16n8k16.row.col.f32.bf16.bf16.f32 "
        "{%0,%1,%2,%3}, {%4,%5,%6,%7}, {%8,%9}, {%0,%1,%2,%3};\n"
        : "+f"(c[0]), "+f"(c[1]), "+f"(c[2]), "+f"(c[3])
        : "r"(a[0]), "r"(a[1]), "r"(a[2]), "r"(a[3]), "r"(b[0]), "r"(b[1]));
}
__device__ __forceinline__ uint32_t packbf(float x, float y) {
    __nv_bfloat162 p = __floats2bfloat162_rn(x, y);
    return *(uint32_t*)&p;
}

__device__ __forceinline__ int win_to_global(int wrow) {
    int b_  = wrow >> 6;
    int n   = wrow & 63;
    int b   = b_ / NWIN;
    int wi  = b_ - b * NWIN;
    int hp  = (wi / 7) * 8 + (n >> 3);
    int wp  = (wi % 7) * 8 + (n & 7);
    int h = hp + 4; if (h >= HH)  h -= HH;
    int w = wp + 4; if (w >= WW_) w -= WW_;
    return b * LL + h * WW_ + w;
}

// ---------------- weight prep: bf16 + transpose to [N][K] ----------------
__global__ void prep_w_kernel(const float* __restrict__ qkv_w,
                              const float* __restrict__ proj_w,
                              const float* __restrict__ fc1_w,
                              const float* __restrict__ fc2_w)
{
    int i = blockIdx.x * 256 + threadIdx.x;
    if (i < 192 * 576) {
        int k = i / 576, n = i % 576;
        g_wb[WOFF_QKV + n * 192 + k] = __float2bfloat16_rn(qkv_w[i]);
    }
    if (i < 192 * 192) {
        int k = i / 192, n = i % 192;
        g_wb[WOFF_PROJ + n * 192 + k] = __float2bfloat16_rn(proj_w[i]);
    }
    if (i < 192 * 768) {
        int k = i / 768, n = i % 768;
        g_wb[WOFF_FC1 + n * 192 + k] = __float2bfloat16_rn(fc1_w[i]);
    }
    if (i < 768 * 192) {
        int k = i / 192, n = i % 192;
        g_wb[WOFF_FC2 + n * 768 + k] = __float2bfloat16_rn(fc2_w[i]);
    }
}

// ---------------- LayerNorm -> bf16 ----------------
template<bool MAP>
__global__ void ln_kernel(const float* __restrict__ x,
                          const float* __restrict__ w,
                          const float* __restrict__ b,
                          __nv_bfloat16* __restrict__ out)
{
    int row = blockIdx.x;
    int tid = threadIdx.x;
    int g = MAP ? win_to_global(row) : row;
    float v = x[(size_t)g * CC + tid];

    __shared__ float sh[12];
    float s = v, s2 = v * v;
    #pragma unroll
    for (int o = 16; o; o >>= 1) {
        s  += __shfl_xor_sync(0xffffffffu, s,  o);
        s2 += __shfl_xor_sync(0xffffffffu, s2, o);
    }
    int wp = tid >> 5;
    if ((tid & 31) == 0) { sh[wp] = s; sh[6 + wp] = s2; }
    __syncthreads();
    float ts = 0.f, ts2 = 0.f;
    #pragma unroll
    for (int i = 0; i < 6; i++) { ts += sh[i]; ts2 += sh[6 + i]; }
    const float inv = 1.f / 192.f;
    float mu  = ts * inv;
    float var = ts2 * inv - mu * mu;
    float rs  = rsqrtf(var + 1e-5f);
    out[(size_t)row * CC + tid] = __float2bfloat16_rn((v - mu) * rs * w[tid] + b[tid]);
}

// ---------------- bf16 tensor-core GEMM with ldmatrix (R8, 2-stage) ----------------
template<int EPI, typename OutT>
__global__ void __launch_bounds__(256)
gemm_bf(const __nv_bfloat16* __restrict__ A, const __nv_bfloat16* __restrict__ Wt,
        const float* __restrict__ bias, const float* __restrict__ res,
        OutT* __restrict__ Cout, int M, int N, int K)
{
    extern __shared__ uint32_t smem[];
    uint32_t* As = smem;                     // [2][BM][LDA2]
    uint32_t* Bs = smem + 2 * BM * LDA2;     // [2][BN][LDB2]

    const int tid  = threadIdx.x;
    const int wid  = tid >> 5, lane = tid & 31;
    const int bm   = blockIdx.y * BM, bn = blockIdx.x * BN;
    const int warp_m = (wid >> 1) * 64;
    const int warp_n = (wid & 1) * 32;
    const int lr = lane >> 2, lc = lane & 3;

    float acc[4][4][4];
    #pragma unroll
    for (int f = 0; f < 4; f++)
        #pragma unroll
        for (int g = 0; g < 4; g++)
            #pragma unroll
            for (int r = 0; r < 4; r++) acc[f][g][r] = 0.f;

    auto load_tiles = [&](int k0, int stage) {
        uint32_t* as = As + stage * (BM * LDA2);
        uint32_t* bs = Bs + stage * (BN * LDB2);
        #pragma unroll
        for (int i = 0; i < 4; i++) {
            int idx = tid + i * 256;
            int r = idx >> 2, c = idx & 3;
            cp_async16(smem_u32(&as[r * LDA2 + c * 4]),
                       A + (size_t)(bm + r) * K + k0 + c * 8);
        }
        {
            int r = tid >> 2, c = tid & 3;
            cp_async16(smem_u32(&bs[r * LDB2 + c * 4]),
                       Wt + (size_t)(bn + r) * K + k0 + c * 8);
        }
        asm volatile("cp.async.commit_group;\n");
    };

    const int g8 = lane >> 3;
    const int a_row = (lane & 7) + ((g8 & 1) << 3);
    const int a_k   = (g8 >> 1) << 2;
    const int b_row = (lane & 7) + ((lane & 16) ? 8 : 0);
    const int b_k   = (lane & 8) ? 4 : 0;

    uint32_t aBase[2], bBase[2];
    #pragma unroll
    for (int st = 0; st < 2; st++) {
        aBase[st] = smem_u32(As + st * (BM * LDA2) + (warp_m + a_row) * LDA2 + a_k);
        bBase[st] = smem_u32(Bs + st * (BN * LDB2) + (warp_n + b_row) * LDB2 + b_k);
    }

    load_tiles(0, 0);
    asm volatile("cp.async.wait_group 0;\n");
    __syncthreads();

    const int KT = K >> 5;
    for (int kt = 0; kt < KT; kt++) {
        int stage = kt & 1;
        if (kt + 1 < KT) load_tiles((kt + 1) << 5, stage ^ 1);

        #pragma unroll
        for (int ks = 0; ks < 2; ks++) {
            uint32_t a[4][4];
            #pragma unroll
            for (int f = 0; f < 4; f++)
                ldsm_x4(a[f], aBase[stage] + (uint32_t)((f * 16 * LDA2 + ks * 8) * 4));
            uint32_t b[4][2];
            #pragma unroll
            for (int gp = 0; gp < 2; gp++) {
                uint32_t r[4];
                ldsm_x4(r, bBase[stage] + (uint32_t)((gp * 16 * LDB2 + ks * 8) * 4));
                b[gp * 2 + 0][0] = r[0]; b[gp * 2 + 0][1] = r[1];
                b[gp * 2 + 1][0] = r[2]; b[gp * 2 + 1][1] = r[3];
            }
            #pragma unroll
            for (int f = 0; f < 4; f++)
                #pragma unroll
                for (int g = 0; g < 4; g++)
                    mma_bf16(acc[f][g], a[f], b[g]);
        }
        asm volatile("cp.async.wait_group 0;\n");
        __syncthreads();
    }

    // epilogue
    #pragma unroll
    for (int f = 0; f < 4; f++) {
        #pragma unroll
        for (int i = 0; i < 2; i++) {
            int m  = bm + warp_m + f * 16 + lr + i * 8;
            int gm = (EPI == 2) ? win_to_global(m) : m;
            #pragma unroll
            for (int g = 0; g < 4; g++) {
                int n = bn + warp_n + g * 8 + lc * 2;
                float v0 = acc[f][g][i * 2 + 0] + bias[n];
                float v1 = acc[f][g][i * 2 + 1] + bias[n + 1];
                if (EPI == 1) {
                    v0 = 0.5f * v0 * (1.f + erff(v0 * 0.70710678118654752f));
                    v1 = 0.5f * v1 * (1.f + erff(v1 * 0.70710678118654752f));
                }
                if (EPI == 0 || EPI == 1) {
                    *(__nv_bfloat162*)((__nv_bfloat16*)Cout + (size_t)m * N + n) =
                        __floats2bfloat162_rn(v0, v1);
                } else {
                    const float* rp = res + (size_t)((EPI == 2) ? gm : m) * N + n;
                    float2 r2 = *(const float2*)rp;
                    v0 += r2.x; v1 += r2.y;
                    *(float2*)((float*)Cout + (size_t)gm * N + n) = make_float2(v0, v1);
                }
            }
        }
    }
}

// ---------------- bf16 tensor-core windowed attention ----------------
// block = (window, head), 64 threads = 2 warps; warp owns 32 query rows.
// S = Q@K^T via mma.m16n8k16 bf16 (Q frags straight from gmem, K in smem),
// softmax in fp32 regs, P packed in-lane to bf16 A-frags (C m16n16 == A m16k16),
// P@V via bf16 mma with V stored dim-major in smem (conflict-free 32-bit B loads).
__global__ void __launch_bounds__(64)
attn_mma_kernel(const __nv_bfloat16* __restrict__ qkv, const float* __restrict__ rpb,
                __nv_bfloat16* __restrict__ out)
{
    const int b_   = blockIdx.x;
    const int h    = blockIdx.y;
    const int tid  = threadIdx.x;
    const int warp = tid >> 5, lane = tid & 31;

    __shared__ uint32_t Ks[NT * 20];     // [key][dim] bf16, row stride 20 words
    __shared__ uint32_t Vt[HD * 36];     // [dim][key] bf16, row stride 36 words
    __shared__ float    bias_s[225];
    __shared__ int      reg_s[NT];

    const __nv_bfloat16* base = qkv + (size_t)b_ * NT * QKVN;

    // K: raw 16B copies into [key][dim] layout
    for (int i = tid; i < 256; i += 64) {
        int r = i >> 2, c = i & 3;
        uint4 v = *(const uint4*)(base + r * QKVN + 192 + h * HD + c * 8);
        *(uint4*)&Ks[r * 20 + c * 4] = v;
    }
    // V: transpose to [dim][key] (scalar bf16; coalesced gmem reads)
    {
        __nv_bfloat16* vt = (__nv_bfloat16*)Vt;
        for (int i = tid; i < NT * HD; i += 64) {
            int k = i >> 5, d = i & 31;
            vt[d * 72 + k] = base[k * QKVN + 384 + h * HD + d];
        }
    }
    for (int i = tid; i < 225; i += 64) bias_s[i] = rpb[i * NHEADS + h];
    {
        int wi = b_ % NWIN;
        int r = tid >> 3, c = tid & 7;
        int gh = (wi / 7) * 8 + r;
        int gw = (wi % 7) * 8 + c;
        reg_s[tid] = ((gh < 48) ? 0 : (gh < 52 ? 1 : 2)) * 3
                   + ((gw < 48) ? 0 : (gw < 52 ? 1 : 2));
    }
    __syncthreads();

    const int m0 = warp * 32;
    const int lr = lane >> 2, lc = lane & 3;

    // Q A-frags straight from gmem (raw bf16 pairs; scale applied post-mma)
    uint32_t qa[2][2][4];
    #pragma unroll
    for (int ks = 0; ks < 2; ks++)
        #pragma unroll
        for (int mf = 0; mf < 2; mf++) {
            const __nv_bfloat16* qp = base + (size_t)(m0 + mf * 16 + lr) * QKVN
                                    + h * HD + ks * 16 + 2 * lc;
            qa[ks][mf][0] = *(const uint32_t*)(qp);
            qa[ks][mf][1] = *(const uint32_t*)(qp + 8 * QKVN);
            qa[ks][mf][2] = *(const uint32_t*)(qp + 8);
            qa[ks][mf][3] = *(const uint32_t*)(qp + 8 * QKVN + 8);
        }

    // S = Q @ K^T : M=32, N=64, K=32 (2 k16 steps)
    float sacc[2][8][4];
    #pragma unroll
    for (int mf = 0; mf < 2; mf++)
        #pragma unroll
        for (int nf = 0; nf < 8; nf++)
            #pragma unroll
            for (int e = 0; e < 4; e++) sacc[mf][nf][e] = 0.f;

    #pragma unroll
    for (int ks = 0; ks < 2; ks++) {
        uint32_t kb[8][2];
        #pragma unroll
        for (int nf = 0; nf < 8; nf++) {
            int w0 = (nf * 8 + lr) * 20 + ks * 8 + lc;
            kb[nf][0] = Ks[w0];
            kb[nf][1] = Ks[w0 + 4];
        }
        #pragma unroll
        for (int mf = 0; mf < 2; mf++)
            #pragma unroll
            for (int nf = 0; nf < 8; nf++)
                mma_bf16(sacc[mf][nf], qa[ks][mf], kb[nf]);
    }

    // scale + bias + mask + softmax (row owned by a 4-lane group)
    #pragma unroll
    for (int mf = 0; mf < 2; mf++) {
        #pragma unroll
        for (int half = 0; half < 2; half++) {
            int row = m0 + mf * 16 + lr + half * 8;
            int r1 = row >> 3, c1 = row & 7, myreg = reg_s[row];
            float mx = -1e30f;
            #pragma unroll
            for (int nf = 0; nf < 8; nf++)
                #pragma unroll
                for (int j = 0; j < 2; j++) {
                    int col = nf * 8 + lc * 2 + j;
                    float v = sacc[mf][nf][half * 2 + j] * SCALE_
                            + bias_s[(r1 - (col >> 3) + 7) * 15 + (c1 - (col & 7) + 7)];
                    if (reg_s[col] != myreg) v -= 100.f;
                    sacc[mf][nf][half * 2 + j] = v;
                    mx = fmaxf(mx, v);
                }
            mx = fmaxf(mx, __shfl_xor_sync(0xffffffffu, mx, 1));
            mx = fmaxf(mx, __shfl_xor_sync(0xffffffffu, mx, 2));
            float sum = 0.f;
            #pragma unroll
            for (int nf = 0; nf < 8; nf++)
                #pragma unroll
                for (int j = 0; j < 2; j++) {
                    float e = __expf(sacc[mf][nf][half * 2 + j] - mx);
                    sacc[mf][nf][half * 2 + j] = e;
                    sum += e;
                }
            sum += __shfl_xor_sync(0xffffffffu, sum, 1);
            sum += __shfl_xor_sync(0xffffffffu, sum, 2);
            float rinv = 1.f / sum;
            #pragma unroll
            for (int nf = 0; nf < 8; nf++)
                #pragma unroll
                for (int j = 0; j < 2; j++)
                    sacc[mf][nf][half * 2 + j] *= rinv;
        }
    }

    // O = P @ V : M=32, N=32, K=64 (4 k16 steps).
    // P C-frags (two adjacent n8 tiles) pack in-lane into one m16k16 A-frag.
    float pacc[2][4][4];
    #pragma unroll
    for (int mf = 0; mf < 2; mf++)
        #pragma unroll
        for (int nf = 0; nf < 4; nf++)
            #pragma unroll
            for (int e = 0; e < 4; e++) pacc[mf][nf][e] = 0.f;

    #pragma unroll
    for (int kc = 0; kc < 4; kc++) {
        uint32_t vb[4][2];
        #pragma unroll
        for (int nf = 0; nf < 4; nf++) {
            int w0 = (nf * 8 + lr) * 36 + kc * 8 + lc;
            vb[nf][0] = Vt[w0];
            vb[nf][1] = Vt[w0 + 4];
        }
        #pragma unroll
        for (int mf = 0; mf < 2; mf++) {
            uint32_t pa[4];
            pa[0] = packbf(sacc[mf][2 * kc][0],     sacc[mf][2 * kc][1]);
            pa[1] = packbf(sacc[mf][2 * kc][2],     sacc[mf][2 * kc][3]);
            pa[2] = packbf(sacc[mf][2 * kc + 1][0], sacc[mf][2 * kc + 1][1]);
            pa[3] = packbf(sacc[mf][2 * kc + 1][2], sacc[mf][2 * kc + 1][3]);
            #pragma unroll
            for (int nf = 0; nf < 4; nf++)
                mma_bf16(pacc[mf][nf], pa, vb[nf]);
        }
    }

    // store bf16 (feeds proj GEMM)
    #pragma unroll
    for (int mf = 0; mf < 2; mf++) {
        int row = m0 + mf * 16 + lr;
        #pragma unroll
        for (int nf = 0; nf < 4; nf++) {
            int col = h * HD + nf * 8 + lc * 2;
            __nv_bfloat16* o = out + (size_t)(b_ * NT + row) * CC + col;
            *(__nv_bfloat162*)o = __floats2bfloat162_rn(pacc[mf][nf][0], pacc[mf][nf][1]);
            *(__nv_bfloat162*)(o + 8 * CC) = __floats2bfloat162_rn(pacc[mf][nf][2], pacc[mf][nf][3]);
        }
    }
}

// ---------------- launch ----------------
extern "C" void kernel_launch(void* const* d_in, const int* in_sizes, int n_in,
                              void* d_out, int out_size)
{
    const float* x      = (const float*)d_in[0];
    const float* ln1_w  = (const float*)d_in[1];
    const float* ln1_b  = (const float*)d_in[2];
    const float* qkv_w  = (const float*)d_in[3];
    const float* qkv_b  = (const float*)d_in[4];
    const float* proj_w = (const float*)d_in[5];
    const float* proj_b = (const float*)d_in[6];
    const float* rpb    = (const float*)d_in[7];
    const float* ln2_w  = (const float*)d_in[8];
    const float* ln2_b  = (const float*)d_in[9];
    const float* fc1_w  = (const float*)d_in[10];
    const float* fc1_b  = (const float*)d_in[11];
    const float* fc2_w  = (const float*)d_in[12];
    const float* fc2_b  = (const float*)d_in[13];
    float* out = (float*)d_out;

    __nv_bfloat16 *xw, *qkv, *attn, *xn2, *h1, *wb;
    cudaGetSymbolAddress((void**)&xw,   g_xw);
    cudaGetSymbolAddress((void**)&qkv,  g_qkv);
    cudaGetSymbolAddress((void**)&attn, g_attn);
    cudaGetSymbolAddress((void**)&xn2,  g_xn2);
    cudaGetSymbolAddress((void**)&h1,   g_h1);
    cudaGetSymbolAddress((void**)&wb,   g_wb);

    cudaFuncSetAttribute(gemm_bf<0, __nv_bfloat16>,
                         cudaFuncAttributeMaxDynamicSharedMemorySize, SMEM_BYTES);
    cudaFuncSetAttribute(gemm_bf<1, __nv_bfloat16>,
                         cudaFuncAttributeMaxDynamicSharedMemorySize, SMEM_BYTES);
    cudaFuncSetAttribute(gemm_bf<2, float>,
                         cudaFuncAttributeMaxDynamicSharedMemorySize, SMEM_BYTES);
    cudaFuncSetAttribute(gemm_bf<3, float>,
                         cudaFuncAttributeMaxDynamicSharedMemorySize, SMEM_BYTES);

    prep_w_kernel<<<(147456 + 255) / 256, 256>>>(qkv_w, proj_w, fc1_w, fc2_w);
    ln_kernel<true><<<MROWS, CC>>>(x, ln1_w, ln1_b, xw);
    gemm_bf<0, __nv_bfloat16><<<dim3(QKVN / BN, MROWS / BM), 256, SMEM_BYTES>>>(
        xw, wb + WOFF_QKV, qkv_b, nullptr, qkv, MROWS, QKVN, CC);
    attn_mma_kernel<<<dim3(BWIN, NHEADS), 64>>>(qkv, rpb, attn);
    gemm_bf<2, float><<<dim3(CC / BN, MROWS / BM), 256, SMEM_BYTES>>>(
        attn, wb + WOFF_PROJ, proj_b, x, out, MROWS, CC, CC);
    ln_kernel<false><<<MROWS, CC>>>(out, ln2_w, ln2_b, xn2);
    gemm_bf<1, __nv_bfloat16><<<dim3(HID / BN, MROWS / BM), 256, SMEM_BYTES>>>(
        xn2, wb + WOFF_FC1, fc1_b, nullptr, h1, MROWS, HID, CC);
    gemm_bf<3, float><<<dim3(CC / BN, MROWS / BM), 256, SMEM_BYTES>>>(
        h1, wb + WOFF_FC2, fc2_b, out, out, MROWS, CC, HID);
}